// round 9
// baseline (speedup 1.0000x reference)
#include <cuda_runtime.h>
#include <cuda_bf16.h>
#include <math.h>
#include <stdint.h>

// ---------------- problem constants ----------------
#define BATCH 32
#define HH 64
#define WW 64
#define CH 192
#define LL (HH*WW)            // 4096
#define NHEAD 6
#define HD 32
#define WSZ 8
#define SHIFT 4
#define NTOK 64
#define NWIN 64
#define MROWS (BATCH*LL)      // 131072
#define CHID (4*CH)           // 768

// ---------------- scratch (device globals; no allocs allowed) ----------------
__device__ __nv_bfloat16 g_xn  [MROWS*CH];
__device__ __nv_bfloat16 g_qkv [MROWS*3*CH];
__device__ __nv_bfloat16 g_attn[MROWS*CH];
__device__ float         g_x2  [MROWS*CH];
__device__ __nv_bfloat16 g_xn2 [MROWS*CH];
__device__ __nv_bfloat16 g_h1  [MROWS*CHID];
// bf16 weights (converted once per launch)
__device__ __nv_bfloat16 g_wq[3*CH*CH];
__device__ __nv_bfloat16 g_wp[CH*CH];
__device__ __nv_bfloat16 g_w1[CHID*CH];
__device__ __nv_bfloat16 g_w2[CH*CHID];

// roll(-4,-4)+window-partition map (self-inverse)
__device__ __forceinline__ int win_to_img_row(int r) {
    int b   = r >> 12;
    int rem = r & 4095;
    int win = rem >> 6;
    int n   = rem & 63;
    int hs  = ((win >> 3) << 3) + (n >> 3);
    int ws  = ((win & 7)  << 3) + (n & 7);
    int hh  = (hs + SHIFT) & 63;
    int ww  = (ws + SHIFT) & 63;
    return (b << 12) + (hh << 6) + ww;
}

// ---------------- asm helpers ----------------
__device__ __forceinline__ uint32_t smem_u32(const void* p) {
    uint32_t a;
    asm("{ .reg .u64 t; cvta.to.shared.u64 t, %1; cvt.u32.u64 %0, t; }" : "=r"(a) : "l"(p));
    return a;
}
__device__ __forceinline__ void cp16(uint32_t dst, const void* src) {
    asm volatile("cp.async.cg.shared.global [%0], [%1], 16;" :: "r"(dst), "l"(src));
}
#define CP_COMMIT() asm volatile("cp.async.commit_group;" ::: "memory")
#define CP_WAIT(n)  asm volatile("cp.async.wait_group %0;" :: "n"(n) : "memory")

#define LDSM4(r0, r1, r2, r3, a) \
    asm volatile("ldmatrix.sync.aligned.m8n8.x4.shared.b16 {%0,%1,%2,%3}, [%4];" \
                 : "=r"(r0), "=r"(r1), "=r"(r2), "=r"(r3) : "r"(a))

__device__ __forceinline__ void mma_bf16(float* d, const unsigned* a, const unsigned* b) {
    asm volatile(
        "mma.sync.aligned.m16n8k16.row.col.f32.bf16.bf16.f32 "
        "{%0,%1,%2,%3}, {%4,%5,%6,%7}, {%8,%9}, {%0,%1,%2,%3};"
        : "+f"(d[0]), "+f"(d[1]), "+f"(d[2]), "+f"(d[3])
        : "r"(a[0]), "r"(a[1]), "r"(a[2]), "r"(a[3]), "r"(b[0]), "r"(b[1]));
}

// ---------------- fp32 -> bf16 weight conversion ----------------
__global__ void cvt_bf16(const float* __restrict__ s, __nv_bfloat16* __restrict__ d, int n) {
    int i = (blockIdx.x * 256 + threadIdx.x) * 4;
    if (i < n) {
        float4 v = *(const float4*)&s[i];
        *(__nv_bfloat162*)&d[i]   = __floats2bfloat162_rn(v.x, v.y);
        *(__nv_bfloat162*)&d[i+2] = __floats2bfloat162_rn(v.z, v.w);
    }
}

// ---------------- LayerNorm: one block per row, 192 threads, bf16 out ----------------
__global__ void ln_kernel(const float* __restrict__ x, const float* __restrict__ g,
                          const float* __restrict__ b, __nv_bfloat16* __restrict__ out) {
    int row = blockIdx.x;
    int t = threadIdx.x;
    float v = x[row*CH + t];
    float s = v, s2 = v*v;
    #pragma unroll
    for (int o = 16; o > 0; o >>= 1) {
        s  += __shfl_down_sync(0xffffffffu, s,  o);
        s2 += __shfl_down_sync(0xffffffffu, s2, o);
    }
    __shared__ float red[12];
    int wid = t >> 5, lane = t & 31;
    if (lane == 0) { red[wid] = s; red[6+wid] = s2; }
    __syncthreads();
    if (t == 0) {
        float a = 0.f, c = 0.f;
        #pragma unroll
        for (int i = 0; i < 6; i++) { a += red[i]; c += red[6+i]; }
        red[0] = a; red[6] = c;
    }
    __syncthreads();
    float mean = red[0] * (1.0f/CH);
    float var  = red[6] * (1.0f/CH) - mean*mean;
    float inv  = rsqrtf(var + 1e-5f);
    out[row*CH + t] = __float2bfloat16((v - mean) * inv * g[t] + b[t]);
}

// ---------------- pipelined bf16 mma GEMM: C[M,N] = A[M,K] @ Bw[N,K]^T ----------------
// 128 threads = 4 warps (2m x 2n), block tile 128x96, warp tile 64x48, BK=64.
// cp.async.cg double-buffered smem; ldmatrix.x4 fragments.
// Smem chunk layout: addr(row, chunk c in 0..7) = base + row*128 + ((c ^ (row&7))*16).
// MODE 0: A gathered via win_to_img_row, +bias, bf16 out          (QKV)
// MODE 1: output scatter via win_to_img_row, +bias+resid, f32 out (proj)
// MODE 2: gelu(acc+bias), bf16 out                                (fc1)
// MODE 3: +bias+resid, f32 out                                    (fc2)
#define STG   28672              // per-stage bytes: A 16KB + B 12KB
#define BOFF  16384
#define GSM   (2*STG + 512)      // + rowIdx

template<int MODE>
__global__ __launch_bounds__(128)
void gemm_cp(const __nv_bfloat16* __restrict__ A, const __nv_bfloat16* __restrict__ Bw,
             const float* __restrict__ bias, const float* __restrict__ resid,
             void* __restrict__ CoutV, int K, int Ncols) {
    extern __shared__ __align__(1024) unsigned char smem[];
    uint32_t sb = smem_u32(smem);
    int* rowIdx = (int*)(smem + 2*STG);

    int tid = threadIdx.x;
    int wid = tid >> 5, lane = tid & 31;
    int rowBase = blockIdx.y * 128;
    int colBase = blockIdx.x * 96;

    {
        int r = rowBase + tid;
        rowIdx[tid] = (MODE == 0) ? win_to_img_row(r) : r;
    }
    __syncthreads();

    // ---- loader precompute: thread owns chunk col (tid&7), rows (tid>>3)+16i ----
    int lc = tid & 7;             // chunk col 0..7 (16B each)
    int lr0 = tid >> 3;           // 0..15
    size_t aSrc[8]; uint32_t aDst[8];
    #pragma unroll
    for (int i = 0; i < 8; i++) {
        int r = lr0 + 16*i;       // 0..127
        aSrc[i] = (size_t)rowIdx[r]*K + 8*lc;
        aDst[i] = (uint32_t)(r*128 + ((lc ^ (r & 7)) << 4));
    }
    size_t bSrc[6]; uint32_t bDst[6];
    #pragma unroll
    for (int i = 0; i < 6; i++) {
        int r = lr0 + 16*i;       // 0..95
        bSrc[i] = (size_t)(colBase + r)*K + 8*lc;
        bDst[i] = (uint32_t)(r*128 + ((lc ^ (r & 7)) << 4));
    }

    const int T = K >> 6;

    // ---- prologue: stages 0,1 ----
    {
        #pragma unroll
        for (int i = 0; i < 8; i++) cp16(sb + aDst[i], A + aSrc[i]);
        #pragma unroll
        for (int i = 0; i < 6; i++) cp16(sb + BOFF + bDst[i], Bw + bSrc[i]);
        CP_COMMIT();
    }
    if (T > 1) {
        #pragma unroll
        for (int i = 0; i < 8; i++) cp16(sb + STG + aDst[i], A + aSrc[i] + 64);
        #pragma unroll
        for (int i = 0; i < 6; i++) cp16(sb + STG + BOFF + bDst[i], Bw + bSrc[i] + 64);
        CP_COMMIT();
    }

    // ---- fragment mapping ----
    int wm = wid >> 1, wn = wid & 1;
    int mW = wm * 64,  nW = wn * 48;
    int q  = lane >> 3, lrl = lane & 7;
    int qh = q >> 1, ql = q & 1;

    float acc[4][6][4];
    #pragma unroll
    for (int mt = 0; mt < 4; mt++)
        #pragma unroll
        for (int nt = 0; nt < 6; nt++)
            #pragma unroll
            for (int i = 0; i < 4; i++) acc[mt][nt][i] = 0.f;

    // per-lane ldmatrix address pieces (row, chunk parity)
    int aRowL[4]; uint32_t aAdrBase[4];
    #pragma unroll
    for (int mt = 0; mt < 4; mt++) {
        int row = mW + 16*mt + ql*8 + lrl;
        aRowL[mt] = row;
        aAdrBase[mt] = (uint32_t)(row*128);
    }
    int bRowL[3]; uint32_t bAdrBase[3];
    #pragma unroll
    for (int p = 0; p < 3; p++) {
        int row = nW + 8*(2*p + qh) + lrl;
        bRowL[p] = row;
        bAdrBase[p] = (uint32_t)(row*128);
    }

    for (int t = 0; t < T; t++) {
        if (t < T-1) { CP_WAIT(1); } else { CP_WAIT(0); }
        __syncthreads();

        uint32_t aB = sb + (t & 1)*STG;
        uint32_t bB = aB + BOFF;

        #pragma unroll
        for (int kk = 0; kk < 4; kk++) {
            int ck = kk*2;
            unsigned aF[4][4], bF[6][2];
            #pragma unroll
            for (int mt = 0; mt < 4; mt++) {
                int ch = ck + qh;                         // A: q0,q1 -> ck ; q2,q3 -> ck+1
                uint32_t ad = aB + aAdrBase[mt] + (uint32_t)(((ch ^ (aRowL[mt] & 7)) << 4));
                LDSM4(aF[mt][0], aF[mt][1], aF[mt][2], aF[mt][3], ad);
            }
            #pragma unroll
            for (int p = 0; p < 3; p++) {
                int ch = ck + ql;                         // B: q0,q2 -> ck ; q1,q3 -> ck+1
                uint32_t bd = bB + bAdrBase[p] + (uint32_t)(((ch ^ (bRowL[p] & 7)) << 4));
                LDSM4(bF[2*p][0], bF[2*p][1], bF[2*p+1][0], bF[2*p+1][1], bd);
            }
            #pragma unroll
            for (int mt = 0; mt < 4; mt++)
                #pragma unroll
                for (int nt = 0; nt < 6; nt++)
                    mma_bf16(acc[mt][nt], aF[mt], bF[nt]);
        }

        if (t + 2 < T) {
            __syncthreads();   // all warps done reading buf (t&1)
            int k0 = (t + 2) << 6;
            uint32_t dB = sb + (t & 1)*STG;
            #pragma unroll
            for (int i = 0; i < 8; i++) cp16(dB + aDst[i], A + aSrc[i] + k0);
            #pragma unroll
            for (int i = 0; i < 6; i++) cp16(dB + BOFF + bDst[i], Bw + bSrc[i] + k0);
            CP_COMMIT();
        }
    }

    // ---- epilogue ----
    int g  = lane >> 2, tg = lane & 3;
    float*         CoutF = (float*)CoutV;
    __nv_bfloat16* CoutB = (__nv_bfloat16*)CoutV;
    #pragma unroll
    for (int mt = 0; mt < 4; mt++) {
        #pragma unroll
        for (int half = 0; half < 2; half++) {
            int row = rowBase + mW + 16*mt + g + half*8;
            int dst = (MODE == 1) ? win_to_img_row(row) : row;
            #pragma unroll
            for (int nt = 0; nt < 6; nt++) {
                int col = colBase + nW + 8*nt + 2*tg;
                float2 bb = *(const float2*)&bias[col];
                float v0 = acc[mt][nt][half*2 + 0] + bb.x;
                float v1 = acc[mt][nt][half*2 + 1] + bb.y;
                if (MODE == 1 || MODE == 3) {
                    float2 rr = *(const float2*)&resid[(size_t)dst*Ncols + col];
                    float2 o; o.x = rr.x + v0; o.y = rr.y + v1;
                    *(float2*)&CoutF[(size_t)dst*Ncols + col] = o;
                } else if (MODE == 2) {
                    float o0 = 0.5f * v0 * (1.0f + erff(v0 * 0.70710678118654752f));
                    float o1 = 0.5f * v1 * (1.0f + erff(v1 * 0.70710678118654752f));
                    *(__nv_bfloat162*)&CoutB[(size_t)dst*Ncols + col] = __floats2bfloat162_rn(o0, o1);
                } else {
                    *(__nv_bfloat162*)&CoutB[(size_t)dst*Ncols + col] = __floats2bfloat162_rn(v0, v1);
                }
            }
        }
    }
}

// ---------------- attention: one block per (head, window), 64 threads ----------------
__device__ __forceinline__ int region_of(int p) {
    return (p < 56) ? 0 : ((p < 60) ? 1 : 2);
}

__global__ __launch_bounds__(64)
void attn_kernel(const __nv_bfloat16* __restrict__ qkv, const float* __restrict__ rpb,
                 __nv_bfloat16* __restrict__ out) {
    int head = blockIdx.x;
    int g    = blockIdx.y;
    int n    = threadIdx.x;

    __shared__ float ks[NTOK][HD];
    __shared__ float vs[NTOK][HD];

    int rowbase = g * NTOK;
    for (int idx = n; idx < NTOK*HD; idx += NTOK) {
        int m = idx >> 5, d = idx & 31;
        const __nv_bfloat16* src = qkv + (size_t)(rowbase + m)*(3*CH) + head*HD;
        ks[m][d] = __bfloat162float(src[CH   + d]);
        vs[m][d] = __bfloat162float(src[2*CH + d]);
    }
    float q[HD];
    {
        const float scale = 0.17677669529663687f;
        const __nv_bfloat16* src = qkv + (size_t)(rowbase + n)*(3*CH) + head*HD;
        #pragma unroll
        for (int d = 0; d < HD; d += 2) {
            __nv_bfloat162 p = *(const __nv_bfloat162*)&src[d];
            q[d]   = __bfloat162float(p.x) * scale;
            q[d+1] = __bfloat162float(p.y) * scale;
        }
    }
    __syncthreads();

    int in_ = n >> 3, jn = n & 7;
    int win = g & 63;
    int wr = win >> 3, wc = win & 7;
    int reg_n = region_of(wr*8 + in_)*3 + region_of(wc*8 + jn);

    float s[NTOK];
    float mx = -1e30f;
    #pragma unroll 4
    for (int m = 0; m < NTOK; m++) {
        float dot = 0.f;
        #pragma unroll
        for (int d = 0; d < HD; d++) dot = fmaf(q[d], ks[m][d], dot);
        int im = m >> 3, jm = m & 7;
        int bidx = (in_ - im + 7)*15 + (jn - jm + 7);
        float bv = rpb[bidx*NHEAD + head];
        int reg_m = region_of(wr*8 + im)*3 + region_of(wc*8 + jm);
        float mv = (reg_n == reg_m) ? 0.f : -100.f;
        float val = dot + bv + mv;
        s[m] = val;
        mx = fmaxf(mx, val);
    }
    float sum = 0.f;
    #pragma unroll 4
    for (int m = 0; m < NTOK; m++) {
        float e = expf(s[m] - mx);
        s[m] = e;
        sum += e;
    }
    float rinv = 1.0f / sum;

    float accv[HD];
    #pragma unroll
    for (int d = 0; d < HD; d++) accv[d] = 0.f;
    #pragma unroll 4
    for (int m = 0; m < NTOK; m++) {
        float p = s[m];
        #pragma unroll
        for (int d = 0; d < HD; d++) accv[d] = fmaf(p, vs[m][d], accv[d]);
    }
    __nv_bfloat16* dst = out + (size_t)(rowbase + n)*CH + head*HD;
    #pragma unroll
    for (int d = 0; d < HD; d += 2)
        *(__nv_bfloat162*)&dst[d] = __floats2bfloat162_rn(accv[d]*rinv, accv[d+1]*rinv);
}

// ---------------- launch ----------------
extern "C" void kernel_launch(void* const* d_in, const int* in_sizes, int n_in,
                              void* d_out, int out_size) {
    const float* x       = (const float*)d_in[0];
    const float* norm1_g = (const float*)d_in[3];
    const float* norm1_b = (const float*)d_in[4];
    const float* qkv_w   = (const float*)d_in[5];
    const float* qkv_b   = (const float*)d_in[6];
    const float* rpb     = (const float*)d_in[7];
    const float* proj_w  = (const float*)d_in[8];
    const float* proj_b  = (const float*)d_in[9];
    const float* norm2_g = (const float*)d_in[10];
    const float* norm2_b = (const float*)d_in[11];
    const float* fc1_w   = (const float*)d_in[12];
    const float* fc1_b   = (const float*)d_in[13];
    const float* fc2_w   = (const float*)d_in[14];
    const float* fc2_b   = (const float*)d_in[15];
    float* out = (float*)d_out;

    __nv_bfloat16 *xn, *qkv, *attn, *xn2, *h1, *wq, *wp, *w1, *w2;
    float *x2;
    cudaGetSymbolAddress((void**)&xn,   g_xn);
    cudaGetSymbolAddress((void**)&qkv,  g_qkv);
    cudaGetSymbolAddress((void**)&attn, g_attn);
    cudaGetSymbolAddress((void**)&x2,   g_x2);
    cudaGetSymbolAddress((void**)&xn2,  g_xn2);
    cudaGetSymbolAddress((void**)&h1,   g_h1);
    cudaGetSymbolAddress((void**)&wq,   g_wq);
    cudaGetSymbolAddress((void**)&wp,   g_wp);
    cudaGetSymbolAddress((void**)&w1,   g_w1);
    cudaGetSymbolAddress((void**)&w2,   g_w2);

    cudaFuncSetAttribute(gemm_cp<0>, cudaFuncAttributeMaxDynamicSharedMemorySize, GSM);
    cudaFuncSetAttribute(gemm_cp<1>, cudaFuncAttributeMaxDynamicSharedMemorySize, GSM);
    cudaFuncSetAttribute(gemm_cp<2>, cudaFuncAttributeMaxDynamicSharedMemorySize, GSM);
    cudaFuncSetAttribute(gemm_cp<3>, cudaFuncAttributeMaxDynamicSharedMemorySize, GSM);

    // 0) weights -> bf16
    cvt_bf16<<<(3*CH*CH)/1024,  256>>>(qkv_w,  wq, 3*CH*CH);
    cvt_bf16<<<(CH*CH)/1024,    256>>>(proj_w, wp, CH*CH);
    cvt_bf16<<<(CHID*CH)/1024,  256>>>(fc1_w,  w1, CHID*CH);
    cvt_bf16<<<(CH*CHID)/1024,  256>>>(fc2_w,  w2, CH*CHID);
    // 1) LN1
    ln_kernel<<<MROWS, CH>>>(x, norm1_g, norm1_b, xn);
    // 2) QKV (gathered A: shift + window partition fused)
    gemm_cp<0><<<dim3(6, MROWS/128), 128, GSM>>>(xn, wq, qkv_b, nullptr, qkv, CH, 3*CH);
    // 3) windowed attention
    attn_kernel<<<dim3(NHEAD, BATCH*NWIN), 64>>>(qkv, rpb, attn);
    // 4) proj + window reverse + roll + residual
    gemm_cp<1><<<dim3(2, MROWS/128), 128, GSM>>>(attn, wp, proj_b, x, x2, CH, CH);
    // 5) LN2
    ln_kernel<<<MROWS, CH>>>(x2, norm2_g, norm2_b, xn2);
    // 6) fc1 + GELU
    gemm_cp<2><<<dim3(8, MROWS/128), 128, GSM>>>(xn2, w1, fc1_b, nullptr, h1, CH, CHID);
    // 7) fc2 + residual -> out
    gemm_cp<3><<<dim3(2, MROWS/128), 128, GSM>>>(h1, w2, fc2_b, x2, out, CHID, CH);
}

// round 10
// speedup vs baseline: 1.4686x; 1.4686x over previous
#include <cuda_runtime.h>
#include <cuda_bf16.h>
#include <math.h>
#include <stdint.h>

// ---------------- problem constants ----------------
#define BATCH 32
#define HH 64
#define WW 64
#define CH 192
#define LL (HH*WW)            // 4096
#define NHEAD 6
#define HD 32
#define WSZ 8
#define SHIFT 4
#define NTOK 64
#define NWIN 64
#define MROWS (BATCH*LL)      // 131072
#define CHID (4*CH)           // 768

// ---------------- scratch (device globals; no allocs allowed) ----------------
__device__ __nv_bfloat16 g_xn  [MROWS*CH];
__device__ __nv_bfloat16 g_qkv [MROWS*3*CH];
__device__ __nv_bfloat16 g_attn[MROWS*CH];
__device__ float         g_x2  [MROWS*CH];
__device__ __nv_bfloat16 g_xn2 [MROWS*CH];
__device__ __nv_bfloat16 g_h1  [MROWS*CHID];
// bf16 weights (converted once per launch)
__device__ __nv_bfloat16 g_wq[3*CH*CH];
__device__ __nv_bfloat16 g_wp[CH*CH];
__device__ __nv_bfloat16 g_w1[CHID*CH];
__device__ __nv_bfloat16 g_w2[CH*CHID];

// roll(-4,-4)+window-partition map (self-inverse)
__device__ __forceinline__ int win_to_img_row(int r) {
    int b   = r >> 12;
    int rem = r & 4095;
    int win = rem >> 6;
    int n   = rem & 63;
    int hs  = ((win >> 3) << 3) + (n >> 3);
    int ws  = ((win & 7)  << 3) + (n & 7);
    int hh  = (hs + SHIFT) & 63;
    int ww  = (ws + SHIFT) & 63;
    return (b << 12) + (hh << 6) + ww;
}

// ---------------- asm helpers ----------------
__device__ __forceinline__ uint32_t smem_u32(const void* p) {
    uint32_t a;
    asm("{ .reg .u64 t; cvta.to.shared.u64 t, %1; cvt.u32.u64 %0, t; }" : "=r"(a) : "l"(p));
    return a;
}
#define LDSM4(r0, r1, r2, r3, a) \
    asm volatile("ldmatrix.sync.aligned.m8n8.x4.shared.b16 {%0,%1,%2,%3}, [%4];" \
                 : "=r"(r0), "=r"(r1), "=r"(r2), "=r"(r3) : "r"(a))

__device__ __forceinline__ void mma_bf16(float* d, const unsigned* a, const unsigned* b) {
    asm volatile(
        "mma.sync.aligned.m16n8k16.row.col.f32.bf16.bf16.f32 "
        "{%0,%1,%2,%3}, {%4,%5,%6,%7}, {%8,%9}, {%0,%1,%2,%3};"
        : "+f"(d[0]), "+f"(d[1]), "+f"(d[2]), "+f"(d[3])
        : "r"(a[0]), "r"(a[1]), "r"(a[2]), "r"(a[3]), "r"(b[0]), "r"(b[1]));
}

// ---------------- fp32 -> bf16 weight conversion ----------------
__global__ void cvt_bf16(const float* __restrict__ s, __nv_bfloat16* __restrict__ d, int n) {
    int i = (blockIdx.x * 256 + threadIdx.x) * 4;
    if (i < n) {
        float4 v = *(const float4*)&s[i];
        *(__nv_bfloat162*)&d[i]   = __floats2bfloat162_rn(v.x, v.y);
        *(__nv_bfloat162*)&d[i+2] = __floats2bfloat162_rn(v.z, v.w);
    }
}

// ---------------- LayerNorm: one block per row, 192 threads, bf16 out ----------------
__global__ void ln_kernel(const float* __restrict__ x, const float* __restrict__ g,
                          const float* __restrict__ b, __nv_bfloat16* __restrict__ out) {
    int row = blockIdx.x;
    int t = threadIdx.x;
    float v = x[row*CH + t];
    float s = v, s2 = v*v;
    #pragma unroll
    for (int o = 16; o > 0; o >>= 1) {
        s  += __shfl_down_sync(0xffffffffu, s,  o);
        s2 += __shfl_down_sync(0xffffffffu, s2, o);
    }
    __shared__ float red[12];
    int wid = t >> 5, lane = t & 31;
    if (lane == 0) { red[wid] = s; red[6+wid] = s2; }
    __syncthreads();
    if (t == 0) {
        float a = 0.f, c = 0.f;
        #pragma unroll
        for (int i = 0; i < 6; i++) { a += red[i]; c += red[6+i]; }
        red[0] = a; red[6] = c;
    }
    __syncthreads();
    float mean = red[0] * (1.0f/CH);
    float var  = red[6] * (1.0f/CH) - mean*mean;
    float inv  = rsqrtf(var + 1e-5f);
    out[row*CH + t] = __float2bfloat16((v - mean) * inv * g[t] + b[t]);
}

// ---------------- bf16 mma GEMM with ldmatrix: C[M,N] = A[M,K] @ Bw[N,K]^T ----------------
// R6 skeleton: 256 threads = 8 warps (4m x 2n), BM=128, BN=96, warp tile 32x48,
// single smem buffer + register prefetch.  NEW: BK=64 (128B rows, 16B chunks,
// phys chunk = c ^ (row&7)) and ldmatrix.x4 fragment loads (validated in R8).
// MODE 0: A gathered via win_to_img_row, +bias, bf16 out          (QKV)
// MODE 1: output scatter via win_to_img_row, +bias+resid, f32 out (proj)
// MODE 2: gelu(acc+bias), bf16 out                                (fc1)
// MODE 3: +bias+resid, f32 out                                    (fc2)
template<int MODE>
__global__ __launch_bounds__(256, 2)
void gemm_lm(const __nv_bfloat16* __restrict__ A, const __nv_bfloat16* __restrict__ Bw,
             const float* __restrict__ bias, const float* __restrict__ resid,
             void* __restrict__ CoutV, int K, int Ncols) {
    __shared__ __align__(128) unsigned char AsB[128*128];   // 16 KB
    __shared__ __align__(128) unsigned char BsB[96*128];    // 12 KB
    __shared__ int rowIdx[128];

    int tid = threadIdx.x;
    int rowBase = blockIdx.y * 128;
    int colBase = blockIdx.x * 96;

    if (tid < 128) {
        int r = rowBase + tid;
        rowIdx[tid] = (MODE == 0) ? win_to_img_row(r) : r;
    }
    __syncthreads();

    uint32_t asb = smem_u32(AsB);
    uint32_t bsb = smem_u32(BsB);

    // ---- loader: thread owns 16B chunk (tid&7) of rows (tid>>3)+32i ----
    int lc = tid & 7;
    int lr0 = tid >> 3;                       // 0..31
    uint32_t aSrc[4], aDst[4];
    #pragma unroll
    for (int i = 0; i < 4; i++) {
        int r = lr0 + 32*i;                   // 0..127
        aSrc[i] = (uint32_t)rowIdx[r]*K + 8*lc;
        aDst[i] = (uint32_t)(r*128 + ((lc ^ (r & 7)) << 4));
    }
    uint32_t bSrc[3], bDst[3];
    #pragma unroll
    for (int i = 0; i < 3; i++) {
        int r = lr0 + 32*i;                   // 0..95
        bSrc[i] = (uint32_t)(colBase + r)*K + 8*lc;
        bDst[i] = (uint32_t)(r*128 + ((lc ^ (r & 7)) << 4));
    }

    // ---- fragment mapping (ldmatrix lane roles) ----
    int w = tid >> 5, lane = tid & 31;
    int wm = w >> 1, wn = w & 1;
    int mW = wm * 32, nW = wn * 48;
    int q  = lane >> 3, lrl = lane & 7;
    int qh = q >> 1, ql = q & 1;

    int aRow[2];
    #pragma unroll
    for (int mt = 0; mt < 2; mt++) aRow[mt] = mW + 16*mt + ql*8 + lrl;
    int bRow[3];
    #pragma unroll
    for (int p = 0; p < 3; p++) bRow[p] = nW + 8*(2*p + qh) + lrl;

    float acc[2][6][4];
    #pragma unroll
    for (int mt = 0; mt < 2; mt++)
        #pragma unroll
        for (int nt = 0; nt < 6; nt++)
            #pragma unroll
            for (int i = 0; i < 4; i++) acc[mt][nt][i] = 0.f;

    const int T = K >> 6;
    uint4 aP[4], bP[3];
    #pragma unroll
    for (int i = 0; i < 4; i++) aP[i] = *(const uint4*)(A + aSrc[i]);
    #pragma unroll
    for (int i = 0; i < 3; i++) bP[i] = *(const uint4*)(Bw + bSrc[i]);

    for (int t = 0; t < T; t++) {
        if (t > 0) __syncthreads();
        #pragma unroll
        for (int i = 0; i < 4; i++) *(uint4*)(AsB + aDst[i]) = aP[i];
        #pragma unroll
        for (int i = 0; i < 3; i++) *(uint4*)(BsB + bDst[i]) = bP[i];
        __syncthreads();

        if (t + 1 < T) {
            int k0 = (t + 1) << 6;
            #pragma unroll
            for (int i = 0; i < 4; i++) aP[i] = *(const uint4*)(A + aSrc[i] + k0);
            #pragma unroll
            for (int i = 0; i < 3; i++) bP[i] = *(const uint4*)(Bw + bSrc[i] + k0);
        }

        #pragma unroll
        for (int kk = 0; kk < 4; kk++) {
            int ck = kk * 2;
            unsigned aF[2][4], bF[6][2];
            #pragma unroll
            for (int mt = 0; mt < 2; mt++) {
                int ch = ck + qh;
                uint32_t ad = asb + (uint32_t)(aRow[mt]*128 + (((ch ^ (aRow[mt] & 7)) << 4)));
                LDSM4(aF[mt][0], aF[mt][1], aF[mt][2], aF[mt][3], ad);
            }
            #pragma unroll
            for (int p = 0; p < 3; p++) {
                int ch = ck + ql;
                uint32_t bd = bsb + (uint32_t)(bRow[p]*128 + (((ch ^ (bRow[p] & 7)) << 4)));
                LDSM4(bF[2*p][0], bF[2*p][1], bF[2*p+1][0], bF[2*p+1][1], bd);
            }
            #pragma unroll
            for (int mt = 0; mt < 2; mt++)
                #pragma unroll
                for (int nt = 0; nt < 6; nt++)
                    mma_bf16(acc[mt][nt], aF[mt], bF[nt]);
        }
    }

    // ---- epilogue (identical to R6) ----
    int g  = lane >> 2, tg = lane & 3;
    float*         CoutF = (float*)CoutV;
    __nv_bfloat16* CoutB = (__nv_bfloat16*)CoutV;
    #pragma unroll
    for (int mt = 0; mt < 2; mt++) {
        #pragma unroll
        for (int half = 0; half < 2; half++) {
            int row = rowBase + mW + 16*mt + g + half*8;
            int dst = (MODE == 1) ? win_to_img_row(row) : row;
            #pragma unroll
            for (int nt = 0; nt < 6; nt++) {
                int col = colBase + nW + 8*nt + 2*tg;
                float2 bb = *(const float2*)&bias[col];
                float v0 = acc[mt][nt][half*2 + 0] + bb.x;
                float v1 = acc[mt][nt][half*2 + 1] + bb.y;
                if (MODE == 1 || MODE == 3) {
                    float2 rr = *(const float2*)&resid[(size_t)dst*Ncols + col];
                    float2 o; o.x = rr.x + v0; o.y = rr.y + v1;
                    *(float2*)&CoutF[(size_t)dst*Ncols + col] = o;
                } else if (MODE == 2) {
                    float o0 = 0.5f * v0 * (1.0f + erff(v0 * 0.70710678118654752f));
                    float o1 = 0.5f * v1 * (1.0f + erff(v1 * 0.70710678118654752f));
                    *(__nv_bfloat162*)&CoutB[(size_t)dst*Ncols + col] = __floats2bfloat162_rn(o0, o1);
                } else {
                    *(__nv_bfloat162*)&CoutB[(size_t)dst*Ncols + col] = __floats2bfloat162_rn(v0, v1);
                }
            }
        }
    }
}

// ---------------- attention: one block per (head, window), 64 threads ----------------
__device__ __forceinline__ int region_of(int p) {
    return (p < 56) ? 0 : ((p < 60) ? 1 : 2);
}

__global__ __launch_bounds__(64)
void attn_kernel(const __nv_bfloat16* __restrict__ qkv, const float* __restrict__ rpb,
                 __nv_bfloat16* __restrict__ out) {
    int head = blockIdx.x;
    int g    = blockIdx.y;
    int n    = threadIdx.x;

    __shared__ float ks[NTOK][HD];
    __shared__ float vs[NTOK][HD];

    int rowbase = g * NTOK;
    for (int idx = n; idx < NTOK*HD; idx += NTOK) {
        int m = idx >> 5, d = idx & 31;
        const __nv_bfloat16* src = qkv + (size_t)(rowbase + m)*(3*CH) + head*HD;
        ks[m][d] = __bfloat162float(src[CH   + d]);
        vs[m][d] = __bfloat162float(src[2*CH + d]);
    }
    float q[HD];
    {
        const float scale = 0.17677669529663687f;
        const __nv_bfloat16* src = qkv + (size_t)(rowbase + n)*(3*CH) + head*HD;
        #pragma unroll
        for (int d = 0; d < HD; d += 2) {
            __nv_bfloat162 p = *(const __nv_bfloat162*)&src[d];
            q[d]   = __bfloat162float(p.x) * scale;
            q[d+1] = __bfloat162float(p.y) * scale;
        }
    }
    __syncthreads();

    int in_ = n >> 3, jn = n & 7;
    int win = g & 63;
    int wr = win >> 3, wc = win & 7;
    int reg_n = region_of(wr*8 + in_)*3 + region_of(wc*8 + jn);

    float s[NTOK];
    float mx = -1e30f;
    #pragma unroll 4
    for (int m = 0; m < NTOK; m++) {
        float dot = 0.f;
        #pragma unroll
        for (int d = 0; d < HD; d++) dot = fmaf(q[d], ks[m][d], dot);
        int im = m >> 3, jm = m & 7;
        int bidx = (in_ - im + 7)*15 + (jn - jm + 7);
        float bv = rpb[bidx*NHEAD + head];
        int reg_m = region_of(wr*8 + im)*3 + region_of(wc*8 + jm);
        float mv = (reg_n == reg_m) ? 0.f : -100.f;
        float val = dot + bv + mv;
        s[m] = val;
        mx = fmaxf(mx, val);
    }
    float sum = 0.f;
    #pragma unroll 4
    for (int m = 0; m < NTOK; m++) {
        float e = expf(s[m] - mx);
        s[m] = e;
        sum += e;
    }
    float rinv = 1.0f / sum;

    float accv[HD];
    #pragma unroll
    for (int d = 0; d < HD; d++) accv[d] = 0.f;
    #pragma unroll 4
    for (int m = 0; m < NTOK; m++) {
        float p = s[m];
        #pragma unroll
        for (int d = 0; d < HD; d++) accv[d] = fmaf(p, vs[m][d], accv[d]);
    }
    __nv_bfloat16* dst = out + (size_t)(rowbase + n)*CH + head*HD;
    #pragma unroll
    for (int d = 0; d < HD; d += 2)
        *(__nv_bfloat162*)&dst[d] = __floats2bfloat162_rn(accv[d]*rinv, accv[d+1]*rinv);
}

// ---------------- launch ----------------
extern "C" void kernel_launch(void* const* d_in, const int* in_sizes, int n_in,
                              void* d_out, int out_size) {
    const float* x       = (const float*)d_in[0];
    const float* norm1_g = (const float*)d_in[3];
    const float* norm1_b = (const float*)d_in[4];
    const float* qkv_w   = (const float*)d_in[5];
    const float* qkv_b   = (const float*)d_in[6];
    const float* rpb     = (const float*)d_in[7];
    const float* proj_w  = (const float*)d_in[8];
    const float* proj_b  = (const float*)d_in[9];
    const float* norm2_g = (const float*)d_in[10];
    const float* norm2_b = (const float*)d_in[11];
    const float* fc1_w   = (const float*)d_in[12];
    const float* fc1_b   = (const float*)d_in[13];
    const float* fc2_w   = (const float*)d_in[14];
    const float* fc2_b   = (const float*)d_in[15];
    float* out = (float*)d_out;

    __nv_bfloat16 *xn, *qkv, *attn, *xn2, *h1, *wq, *wp, *w1, *w2;
    float *x2;
    cudaGetSymbolAddress((void**)&xn,   g_xn);
    cudaGetSymbolAddress((void**)&qkv,  g_qkv);
    cudaGetSymbolAddress((void**)&attn, g_attn);
    cudaGetSymbolAddress((void**)&x2,   g_x2);
    cudaGetSymbolAddress((void**)&xn2,  g_xn2);
    cudaGetSymbolAddress((void**)&h1,   g_h1);
    cudaGetSymbolAddress((void**)&wq,   g_wq);
    cudaGetSymbolAddress((void**)&wp,   g_wp);
    cudaGetSymbolAddress((void**)&w1,   g_w1);
    cudaGetSymbolAddress((void**)&w2,   g_w2);

    // 0) weights -> bf16
    cvt_bf16<<<(3*CH*CH)/1024,  256>>>(qkv_w,  wq, 3*CH*CH);
    cvt_bf16<<<(CH*CH)/1024,    256>>>(proj_w, wp, CH*CH);
    cvt_bf16<<<(CHID*CH)/1024,  256>>>(fc1_w,  w1, CHID*CH);
    cvt_bf16<<<(CH*CHID)/1024,  256>>>(fc2_w,  w2, CH*CHID);
    // 1) LN1
    ln_kernel<<<MROWS, CH>>>(x, norm1_g, norm1_b, xn);
    // 2) QKV (gathered A: shift + window partition fused)
    gemm_lm<0><<<dim3(6, MROWS/128), 256>>>(xn, wq, qkv_b, nullptr, qkv, CH, 3*CH);
    // 3) windowed attention
    attn_kernel<<<dim3(NHEAD, BATCH*NWIN), 64>>>(qkv, rpb, attn);
    // 4) proj + window reverse + roll + residual
    gemm_lm<1><<<dim3(2, MROWS/128), 256>>>(attn, wp, proj_b, x, x2, CH, CH);
    // 5) LN2
    ln_kernel<<<MROWS, CH>>>(x2, norm2_g, norm2_b, xn2);
    // 6) fc1 + GELU
    gemm_lm<2><<<dim3(8, MROWS/128), 256>>>(xn2, w1, fc1_b, nullptr, h1, CH, CHID);
    // 7) fc2 + residual -> out
    gemm_lm<3><<<dim3(2, MROWS/128), 256>>>(h1, w2, fc2_b, x2, out, CHID, CH);
}

// round 11
// speedup vs baseline: 1.7985x; 1.2246x over previous
#include <cuda_runtime.h>
#include <cuda_bf16.h>
#include <math.h>
#include <stdint.h>

// ---------------- problem constants ----------------
#define BATCH 32
#define HH 64
#define WW 64
#define CH 192
#define LL (HH*WW)            // 4096
#define NHEAD 6
#define HD 32
#define WSZ 8
#define SHIFT 4
#define NTOK 64
#define NWIN 64
#define MROWS (BATCH*LL)      // 131072
#define CHID (4*CH)           // 768

// ---------------- scratch (device globals; no allocs allowed) ----------------
__device__ __nv_bfloat16 g_xn  [MROWS*CH];
__device__ __nv_bfloat16 g_qkv [MROWS*3*CH];
__device__ __nv_bfloat16 g_attn[MROWS*CH];
__device__ float         g_x2  [MROWS*CH];
__device__ __nv_bfloat16 g_xn2 [MROWS*CH];
__device__ __nv_bfloat16 g_h1  [MROWS*CHID];
// bf16 weights (converted once per launch)
__device__ __nv_bfloat16 g_wq[3*CH*CH];     // 110592
__device__ __nv_bfloat16 g_wp[CH*CH];       // 36864
__device__ __nv_bfloat16 g_w1[CHID*CH];     // 147456
__device__ __nv_bfloat16 g_w2[CH*CHID];     // 147456

// roll(-4,-4)+window-partition map (self-inverse)
__device__ __forceinline__ int win_to_img_row(int r) {
    int b   = r >> 12;
    int rem = r & 4095;
    int win = rem >> 6;
    int n   = rem & 63;
    int hs  = ((win >> 3) << 3) + (n >> 3);
    int ws  = ((win & 7)  << 3) + (n & 7);
    int hh  = (hs + SHIFT) & 63;
    int ww  = (ws + SHIFT) & 63;
    return (b << 12) + (hh << 6) + ww;
}

// ---------------- asm helpers ----------------
__device__ __forceinline__ uint32_t smem_u32(const void* p) {
    uint32_t a;
    asm("{ .reg .u64 t; cvta.to.shared.u64 t, %1; cvt.u32.u64 %0, t; }" : "=r"(a) : "l"(p));
    return a;
}
__device__ __forceinline__ void cp16(uint32_t dst, const void* src) {
    asm volatile("cp.async.cg.shared.global [%0], [%1], 16;" :: "r"(dst), "l"(src));
}
#define CP_COMMIT() asm volatile("cp.async.commit_group;" ::: "memory")
#define CP_WAIT(n)  asm volatile("cp.async.wait_group %0;" :: "n"(n) : "memory")
#define LDSM4(r0, r1, r2, r3, a) \
    asm volatile("ldmatrix.sync.aligned.m8n8.x4.shared.b16 {%0,%1,%2,%3}, [%4];" \
                 : "=r"(r0), "=r"(r1), "=r"(r2), "=r"(r3) : "r"(a))

__device__ __forceinline__ void mma_bf16(float* d, const unsigned* a, const unsigned* b) {
    asm volatile(
        "mma.sync.aligned.m16n8k16.row.col.f32.bf16.bf16.f32 "
        "{%0,%1,%2,%3}, {%4,%5,%6,%7}, {%8,%9}, {%0,%1,%2,%3};"
        : "+f"(d[0]), "+f"(d[1]), "+f"(d[2]), "+f"(d[3])
        : "r"(a[0]), "r"(a[1]), "r"(a[2]), "r"(a[3]), "r"(b[0]), "r"(b[1]));
}

// ---------------- fused fp32 -> bf16 weight conversion (all 4 weights) ----------------
#define NWQ (3*CH*CH)
#define NWP (CH*CH)
#define NW1 (CHID*CH)
#define NW2 (CH*CHID)
__global__ void cvt_all(const float* __restrict__ wq, const float* __restrict__ wp,
                        const float* __restrict__ w1, const float* __restrict__ w2,
                        __nv_bfloat16* __restrict__ dq, __nv_bfloat16* __restrict__ dp,
                        __nv_bfloat16* __restrict__ d1, __nv_bfloat16* __restrict__ d2) {
    int i = (blockIdx.x * 256 + threadIdx.x) * 4;
    const float* s; __nv_bfloat16* d; int off;
    if (i < NWQ)                       { s = wq; d = dq; off = i; }
    else if (i < NWQ+NWP)              { s = wp; d = dp; off = i - NWQ; }
    else if (i < NWQ+NWP+NW1)          { s = w1; d = d1; off = i - NWQ - NWP; }
    else if (i < NWQ+NWP+NW1+NW2)      { s = w2; d = d2; off = i - NWQ - NWP - NW1; }
    else return;
    float4 v = *(const float4*)&s[off];
    *(__nv_bfloat162*)&d[off]   = __floats2bfloat162_rn(v.x, v.y);
    *(__nv_bfloat162*)&d[off+2] = __floats2bfloat162_rn(v.z, v.w);
}

// ---------------- LayerNorm: one warp per row, 8 rows per 256-thread block ----------------
__global__ __launch_bounds__(256)
void ln_kernel(const float* __restrict__ x, const float* __restrict__ g,
               const float* __restrict__ b, __nv_bfloat16* __restrict__ out) {
    int w = threadIdx.x >> 5, lane = threadIdx.x & 31;
    int row = blockIdx.x * 8 + w;
    const float* xr = x + (size_t)row * CH;
    float v[6];
    float s = 0.f, s2 = 0.f;
    #pragma unroll
    for (int i = 0; i < 6; i++) {
        v[i] = xr[lane + 32*i];
        s  += v[i];
        s2 += v[i]*v[i];
    }
    #pragma unroll
    for (int o = 16; o > 0; o >>= 1) {
        s  += __shfl_xor_sync(0xffffffffu, s,  o);
        s2 += __shfl_xor_sync(0xffffffffu, s2, o);
    }
    float mean = s * (1.0f/CH);
    float var  = s2 * (1.0f/CH) - mean*mean;
    float inv  = rsqrtf(var + 1e-5f);
    __nv_bfloat16* orow = out + (size_t)row * CH;
    #pragma unroll
    for (int i = 0; i < 6; i++) {
        int c = lane + 32*i;
        orow[c] = __float2bfloat16((v[i] - mean) * inv * g[c] + b[c]);
    }
}

// ---------------- bf16 mma GEMM: cp.async double-buffer + ldmatrix ----------------
// 256 threads = 8 warps (4m x 2n), BM=128, BN=96, BK=64, warp tile 32x48.
// Smem: 2 stages of (A 16KB + B 12KB); chunk swizzle phys = c ^ (row&7).
// MODE 0: A gathered via win_to_img_row, +bias, bf16 out          (QKV)
// MODE 1: output scatter via win_to_img_row, +bias+resid, f32 out (proj)
// MODE 2: gelu(acc+bias), bf16 out                                (fc1)
// MODE 3: +bias+resid, f32 out                                    (fc2)
#define STG   28672
#define BOFF  16384
#define GSM   (2*STG + 512)

template<int MODE>
__global__ __launch_bounds__(256, 2)
void gemm_lm(const __nv_bfloat16* __restrict__ A, const __nv_bfloat16* __restrict__ Bw,
             const float* __restrict__ bias, const float* __restrict__ resid,
             void* __restrict__ CoutV, int K, int Ncols) {
    extern __shared__ __align__(1024) unsigned char smem[];
    uint32_t sb = smem_u32(smem);
    int* rowIdx = (int*)(smem + 2*STG);

    int tid = threadIdx.x;
    int rowBase = blockIdx.y * 128;
    int colBase = blockIdx.x * 96;

    if (tid < 128) {
        int r = rowBase + tid;
        rowIdx[tid] = (MODE == 0) ? win_to_img_row(r) : r;
    }
    __syncthreads();

    // ---- loader: thread owns 16B chunk (tid&7) of rows (tid>>3)+32i ----
    int lc = tid & 7;
    int lr0 = tid >> 3;                       // 0..31
    const char* aPtr[4]; uint32_t aDst[4];
    #pragma unroll
    for (int i = 0; i < 4; i++) {
        int r = lr0 + 32*i;                   // 0..127
        aPtr[i] = (const char*)(A + (size_t)rowIdx[r]*K + 8*lc);
        aDst[i] = (uint32_t)(r*128 + ((lc ^ (r & 7)) << 4));
    }
    const char* bPtr[3]; uint32_t bDst[3];
    #pragma unroll
    for (int i = 0; i < 3; i++) {
        int r = lr0 + 32*i;                   // 0..95
        bPtr[i] = (const char*)(Bw + (size_t)(colBase + r)*K + 8*lc);
        bDst[i] = (uint32_t)(r*128 + ((lc ^ (r & 7)) << 4));
    }

    const int T = K >> 6;

    // ---- prologue: stages 0,1 ----
    {
        #pragma unroll
        for (int i = 0; i < 4; i++) cp16(sb + aDst[i], aPtr[i]);
        #pragma unroll
        for (int i = 0; i < 3; i++) cp16(sb + BOFF + bDst[i], bPtr[i]);
        CP_COMMIT();
        #pragma unroll
        for (int i = 0; i < 4; i++) cp16(sb + STG + aDst[i], aPtr[i] + 128);
        #pragma unroll
        for (int i = 0; i < 3; i++) cp16(sb + STG + BOFF + bDst[i], bPtr[i] + 128);
        CP_COMMIT();
    }

    // ---- fragment mapping (ldmatrix lane roles) ----
    int w = tid >> 5, lane = tid & 31;
    int wm = w >> 1, wn = w & 1;
    int mW = wm * 32, nW = wn * 48;
    int q  = lane >> 3, lrl = lane & 7;
    int qh = q >> 1, ql = q & 1;

    int aRow[2];
    #pragma unroll
    for (int mt = 0; mt < 2; mt++) aRow[mt] = mW + 16*mt + ql*8 + lrl;
    int bRow[3];
    #pragma unroll
    for (int p = 0; p < 3; p++) bRow[p] = nW + 8*(2*p + qh) + lrl;

    float acc[2][6][4];
    #pragma unroll
    for (int mt = 0; mt < 2; mt++)
        #pragma unroll
        for (int nt = 0; nt < 6; nt++)
            #pragma unroll
            for (int i = 0; i < 4; i++) acc[mt][nt][i] = 0.f;

    for (int t = 0; t < T; t++) {
        if (t + 1 < T) { CP_WAIT(1); } else { CP_WAIT(0); }
        __syncthreads();

        uint32_t aB = sb + (uint32_t)(t & 1) * STG;
        uint32_t bB = aB + BOFF;

        #pragma unroll
        for (int kk = 0; kk < 4; kk++) {
            int ck = kk * 2;
            unsigned aF[2][4], bF[6][2];
            #pragma unroll
            for (int mt = 0; mt < 2; mt++) {
                int ch = ck + qh;
                uint32_t ad = aB + (uint32_t)(aRow[mt]*128 + (((ch ^ (aRow[mt] & 7)) << 4)));
                LDSM4(aF[mt][0], aF[mt][1], aF[mt][2], aF[mt][3], ad);
            }
            #pragma unroll
            for (int p = 0; p < 3; p++) {
                int ch = ck + ql;
                uint32_t bd = bB + (uint32_t)(bRow[p]*128 + (((ch ^ (bRow[p] & 7)) << 4)));
                LDSM4(bF[2*p][0], bF[2*p][1], bF[2*p+1][0], bF[2*p+1][1], bd);
            }
            #pragma unroll
            for (int mt = 0; mt < 2; mt++)
                #pragma unroll
                for (int nt = 0; nt < 6; nt++)
                    mma_bf16(acc[mt][nt], aF[mt], bF[nt]);
        }

        if (t + 2 < T) {
            __syncthreads();                   // all warps done reading this buf
            int k0 = (t + 2) << 7;             // byte offset: 64 bf16 = 128 B
            uint32_t dB = sb + (uint32_t)(t & 1) * STG;
            #pragma unroll
            for (int i = 0; i < 4; i++) cp16(dB + aDst[i], aPtr[i] + k0);
            #pragma unroll
            for (int i = 0; i < 3; i++) cp16(dB + BOFF + bDst[i], bPtr[i] + k0);
            CP_COMMIT();
        }
    }

    // ---- epilogue ----
    int g  = lane >> 2, tg = lane & 3;
    float*         CoutF = (float*)CoutV;
    __nv_bfloat16* CoutB = (__nv_bfloat16*)CoutV;
    #pragma unroll
    for (int mt = 0; mt < 2; mt++) {
        #pragma unroll
        for (int half = 0; half < 2; half++) {
            int row = rowBase + mW + 16*mt + g + half*8;
            int dst = (MODE == 1) ? win_to_img_row(row) : row;
            #pragma unroll
            for (int nt = 0; nt < 6; nt++) {
                int col = colBase + nW + 8*nt + 2*tg;
                float2 bb = *(const float2*)&bias[col];
                float v0 = acc[mt][nt][half*2 + 0] + bb.x;
                float v1 = acc[mt][nt][half*2 + 1] + bb.y;
                if (MODE == 1 || MODE == 3) {
                    float2 rr = *(const float2*)&resid[(size_t)dst*Ncols + col];
                    float2 o; o.x = rr.x + v0; o.y = rr.y + v1;
                    *(float2*)&CoutF[(size_t)dst*Ncols + col] = o;
                } else if (MODE == 2) {
                    float o0 = 0.5f * v0 * (1.0f + erff(v0 * 0.70710678118654752f));
                    float o1 = 0.5f * v1 * (1.0f + erff(v1 * 0.70710678118654752f));
                    *(__nv_bfloat162*)&CoutB[(size_t)dst*Ncols + col] = __floats2bfloat162_rn(o0, o1);
                } else {
                    *(__nv_bfloat162*)&CoutB[(size_t)dst*Ncols + col] = __floats2bfloat162_rn(v0, v1);
                }
            }
        }
    }
}

// ---------------- attention: one block per (head, window), 64 threads ----------------
__device__ __forceinline__ int region_of(int p) {
    return (p < 56) ? 0 : ((p < 60) ? 1 : 2);
}

__global__ __launch_bounds__(64)
void attn_kernel(const __nv_bfloat16* __restrict__ qkv, const float* __restrict__ rpb,
                 __nv_bfloat16* __restrict__ out) {
    int head = blockIdx.x;
    int g    = blockIdx.y;
    int n    = threadIdx.x;

    __shared__ float ks[NTOK][HD];
    __shared__ float vs[NTOK][HD];

    int rowbase = g * NTOK;
    for (int idx = n; idx < NTOK*HD; idx += NTOK) {
        int m = idx >> 5, d = idx & 31;
        const __nv_bfloat16* src = qkv + (size_t)(rowbase + m)*(3*CH) + head*HD;
        ks[m][d] = __bfloat162float(src[CH   + d]);
        vs[m][d] = __bfloat162float(src[2*CH + d]);
    }
    float q[HD];
    {
        const float scale = 0.17677669529663687f;
        const __nv_bfloat16* src = qkv + (size_t)(rowbase + n)*(3*CH) + head*HD;
        #pragma unroll
        for (int d = 0; d < HD; d += 2) {
            __nv_bfloat162 p = *(const __nv_bfloat162*)&src[d];
            q[d]   = __bfloat162float(p.x) * scale;
            q[d+1] = __bfloat162float(p.y) * scale;
        }
    }
    __syncthreads();

    int in_ = n >> 3, jn = n & 7;
    int win = g & 63;
    int wr = win >> 3, wc = win & 7;
    int reg_n = region_of(wr*8 + in_)*3 + region_of(wc*8 + jn);

    float s[NTOK];
    float mx = -1e30f;
    #pragma unroll 4
    for (int m = 0; m < NTOK; m++) {
        float dot = 0.f;
        #pragma unroll
        for (int d = 0; d < HD; d++) dot = fmaf(q[d], ks[m][d], dot);
        int im = m >> 3, jm = m & 7;
        int bidx = (in_ - im + 7)*15 + (jn - jm + 7);
        float bv = rpb[bidx*NHEAD + head];
        int reg_m = region_of(wr*8 + im)*3 + region_of(wc*8 + jm);
        float mv = (reg_n == reg_m) ? 0.f : -100.f;
        float val = dot + bv + mv;
        s[m] = val;
        mx = fmaxf(mx, val);
    }
    float sum = 0.f;
    #pragma unroll 4
    for (int m = 0; m < NTOK; m++) {
        float e = expf(s[m] - mx);
        s[m] = e;
        sum += e;
    }
    float rinv = 1.0f / sum;

    float accv[HD];
    #pragma unroll
    for (int d = 0; d < HD; d++) accv[d] = 0.f;
    #pragma unroll 4
    for (int m = 0; m < NTOK; m++) {
        float p = s[m];
        #pragma unroll
        for (int d = 0; d < HD; d++) accv[d] = fmaf(p, vs[m][d], accv[d]);
    }
    __nv_bfloat16* dst = out + (size_t)(rowbase + n)*CH + head*HD;
    #pragma unroll
    for (int d = 0; d < HD; d += 2)
        *(__nv_bfloat162*)&dst[d] = __floats2bfloat162_rn(accv[d]*rinv, accv[d+1]*rinv);
}

// ---------------- launch ----------------
extern "C" void kernel_launch(void* const* d_in, const int* in_sizes, int n_in,
                              void* d_out, int out_size) {
    const float* x       = (const float*)d_in[0];
    const float* norm1_g = (const float*)d_in[3];
    const float* norm1_b = (const float*)d_in[4];
    const float* qkv_w   = (const float*)d_in[5];
    const float* qkv_b   = (const float*)d_in[6];
    const float* rpb     = (const float*)d_in[7];
    const float* proj_w  = (const float*)d_in[8];
    const float* proj_b  = (const float*)d_in[9];
    const float* norm2_g = (const float*)d_in[10];
    const float* norm2_b = (const float*)d_in[11];
    const float* fc1_w   = (const float*)d_in[12];
    const float* fc1_b   = (const float*)d_in[13];
    const float* fc2_w   = (const float*)d_in[14];
    const float* fc2_b   = (const float*)d_in[15];
    float* out = (float*)d_out;

    __nv_bfloat16 *xn, *qkv, *attn, *xn2, *h1, *wq, *wp, *w1, *w2;
    float *x2;
    cudaGetSymbolAddress((void**)&xn,   g_xn);
    cudaGetSymbolAddress((void**)&qkv,  g_qkv);
    cudaGetSymbolAddress((void**)&attn, g_attn);
    cudaGetSymbolAddress((void**)&x2,   g_x2);
    cudaGetSymbolAddress((void**)&xn2,  g_xn2);
    cudaGetSymbolAddress((void**)&h1,   g_h1);
    cudaGetSymbolAddress((void**)&wq,   g_wq);
    cudaGetSymbolAddress((void**)&wp,   g_wp);
    cudaGetSymbolAddress((void**)&w1,   g_w1);
    cudaGetSymbolAddress((void**)&w2,   g_w2);

    cudaFuncSetAttribute(gemm_lm<0>, cudaFuncAttributeMaxDynamicSharedMemorySize, GSM);
    cudaFuncSetAttribute(gemm_lm<1>, cudaFuncAttributeMaxDynamicSharedMemorySize, GSM);
    cudaFuncSetAttribute(gemm_lm<2>, cudaFuncAttributeMaxDynamicSharedMemorySize, GSM);
    cudaFuncSetAttribute(gemm_lm<3>, cudaFuncAttributeMaxDynamicSharedMemorySize, GSM);

    // 0) all weights -> bf16 (single kernel)
    cvt_all<<<(NWQ+NWP+NW1+NW2)/1024, 256>>>(qkv_w, proj_w, fc1_w, fc2_w, wq, wp, w1, w2);
    // 1) LN1
    ln_kernel<<<MROWS/8, 256>>>(x, norm1_g, norm1_b, xn);
    // 2) QKV (gathered A: shift + window partition fused)
    gemm_lm<0><<<dim3(6, MROWS/128), 256, GSM>>>(xn, wq, qkv_b, nullptr, qkv, CH, 3*CH);
    // 3) windowed attention
    attn_kernel<<<dim3(NHEAD, BATCH*NWIN), 64>>>(qkv, rpb, attn);
    // 4) proj + window reverse + roll + residual
    gemm_lm<1><<<dim3(2, MROWS/128), 256, GSM>>>(attn, wp, proj_b, x, x2, CH, CH);
    // 5) LN2
    ln_kernel<<<MROWS/8, 256>>>(x2, norm2_g, norm2_b, xn2);
    // 6) fc1 + GELU
    gemm_lm<2><<<dim3(8, MROWS/128), 256, GSM>>>(xn2, w1, fc1_b, nullptr, h1, CH, CHID);
    // 7) fc2 + residual -> out
    gemm_lm<3><<<dim3(2, MROWS/128), 256, GSM>>>(h1, w2, fc2_b, x2, out, CHID, CH);
}

// round 12
// speedup vs baseline: 2.5978x; 1.4444x over previous
#include <cuda_runtime.h>
#include <cuda_bf16.h>
#include <math.h>
#include <stdint.h>

// ---------------- problem constants ----------------
#define BATCH 32
#define HH 64
#define WW 64
#define CH 192
#define LL (HH*WW)            // 4096
#define NHEAD 6
#define HD 32
#define WSZ 8
#define SHIFT 4
#define NTOK 64
#define NWIN 64
#define MROWS (BATCH*LL)      // 131072
#define CHID (4*CH)           // 768

// ---------------- scratch (device globals; no allocs allowed) ----------------
__device__ __nv_bfloat16 g_xn  [MROWS*CH];
__device__ __nv_bfloat16 g_qkv [MROWS*3*CH];
__device__ __nv_bfloat16 g_attn[MROWS*CH];
__device__ float         g_x2  [MROWS*CH];
__device__ __nv_bfloat16 g_xn2 [MROWS*CH];
__device__ __nv_bfloat16 g_h1  [MROWS*CHID];
// bf16 weights (converted once per launch)
__device__ __nv_bfloat16 g_wq[3*CH*CH];
__device__ __nv_bfloat16 g_wp[CH*CH];
__device__ __nv_bfloat16 g_w1[CHID*CH];
__device__ __nv_bfloat16 g_w2[CH*CHID];

// roll(-4,-4)+window-partition map (self-inverse)
__device__ __forceinline__ int win_to_img_row(int r) {
    int b   = r >> 12;
    int rem = r & 4095;
    int win = rem >> 6;
    int n   = rem & 63;
    int hs  = ((win >> 3) << 3) + (n >> 3);
    int ws  = ((win & 7)  << 3) + (n & 7);
    int hh  = (hs + SHIFT) & 63;
    int ww  = (ws + SHIFT) & 63;
    return (b << 12) + (hh << 6) + ww;
}

// ---------------- asm helpers ----------------
__device__ __forceinline__ uint32_t smem_u32(const void* p) {
    uint32_t a;
    asm("{ .reg .u64 t; cvta.to.shared.u64 t, %1; cvt.u32.u64 %0, t; }" : "=r"(a) : "l"(p));
    return a;
}
__device__ __forceinline__ void cp16(uint32_t dst, const void* src) {
    asm volatile("cp.async.cg.shared.global [%0], [%1], 16;" :: "r"(dst), "l"(src));
}
#define CP_COMMIT() asm volatile("cp.async.commit_group;" ::: "memory")
#define CP_WAIT(n)  asm volatile("cp.async.wait_group %0;" :: "n"(n) : "memory")
#define LDSM4(r0, r1, r2, r3, a) \
    asm volatile("ldmatrix.sync.aligned.m8n8.x4.shared.b16 {%0,%1,%2,%3}, [%4];" \
                 : "=r"(r0), "=r"(r1), "=r"(r2), "=r"(r3) : "r"(a))
#define LDSM4T(r0, r1, r2, r3, a) \
    asm volatile("ldmatrix.sync.aligned.m8n8.x4.trans.shared.b16 {%0,%1,%2,%3}, [%4];" \
                 : "=r"(r0), "=r"(r1), "=r"(r2), "=r"(r3) : "r"(a))

__device__ __forceinline__ void mma_bf16(float* d, const unsigned* a, const unsigned* b) {
    asm volatile(
        "mma.sync.aligned.m16n8k16.row.col.f32.bf16.bf16.f32 "
        "{%0,%1,%2,%3}, {%4,%5,%6,%7}, {%8,%9}, {%0,%1,%2,%3};"
        : "+f"(d[0]), "+f"(d[1]), "+f"(d[2]), "+f"(d[3])
        : "r"(a[0]), "r"(a[1]), "r"(a[2]), "r"(a[3]), "r"(b[0]), "r"(b[1]));
}
__device__ __forceinline__ unsigned pack_bf16(float lo, float hi) {
    __nv_bfloat162 h = __floats2bfloat162_rn(lo, hi);
    return *(unsigned*)&h;
}

// ---------------- fused fp32 -> bf16 weight conversion ----------------
#define NWQ (3*CH*CH)
#define NWP (CH*CH)
#define NW1 (CHID*CH)
#define NW2 (CH*CHID)
__global__ void cvt_all(const float* __restrict__ wq, const float* __restrict__ wp,
                        const float* __restrict__ w1, const float* __restrict__ w2,
                        __nv_bfloat16* __restrict__ dq, __nv_bfloat16* __restrict__ dp,
                        __nv_bfloat16* __restrict__ d1, __nv_bfloat16* __restrict__ d2) {
    int i = (blockIdx.x * 256 + threadIdx.x) * 4;
    const float* s; __nv_bfloat16* d; int off;
    if (i < NWQ)                       { s = wq; d = dq; off = i; }
    else if (i < NWQ+NWP)              { s = wp; d = dp; off = i - NWQ; }
    else if (i < NWQ+NWP+NW1)          { s = w1; d = d1; off = i - NWQ - NWP; }
    else if (i < NWQ+NWP+NW1+NW2)      { s = w2; d = d2; off = i - NWQ - NWP - NW1; }
    else return;
    float4 v = *(const float4*)&s[off];
    *(__nv_bfloat162*)&d[off]   = __floats2bfloat162_rn(v.x, v.y);
    *(__nv_bfloat162*)&d[off+2] = __floats2bfloat162_rn(v.z, v.w);
}

// ---------------- LayerNorm: one warp per row ----------------
__global__ __launch_bounds__(256)
void ln_kernel(const float* __restrict__ x, const float* __restrict__ g,
               const float* __restrict__ b, __nv_bfloat16* __restrict__ out) {
    int w = threadIdx.x >> 5, lane = threadIdx.x & 31;
    int row = blockIdx.x * 8 + w;
    const float* xr = x + (size_t)row * CH;
    float v[6];
    float s = 0.f, s2 = 0.f;
    #pragma unroll
    for (int i = 0; i < 6; i++) {
        v[i] = xr[lane + 32*i];
        s  += v[i];
        s2 += v[i]*v[i];
    }
    #pragma unroll
    for (int o = 16; o > 0; o >>= 1) {
        s  += __shfl_xor_sync(0xffffffffu, s,  o);
        s2 += __shfl_xor_sync(0xffffffffu, s2, o);
    }
    float mean = s * (1.0f/CH);
    float var  = s2 * (1.0f/CH) - mean*mean;
    float inv  = rsqrtf(var + 1e-5f);
    __nv_bfloat16* orow = out + (size_t)row * CH;
    #pragma unroll
    for (int i = 0; i < 6; i++) {
        int c = lane + 32*i;
        orow[c] = __float2bfloat16((v[i] - mean) * inv * g[c] + b[c]);
    }
}

// ---------------- bf16 mma GEMM: cp.async double-buffer + ldmatrix (R10 winner) ----------------
#define STG   28672
#define BOFF  16384
#define GSM   (2*STG + 512)

template<int MODE>
__global__ __launch_bounds__(256, 2)
void gemm_lm(const __nv_bfloat16* __restrict__ A, const __nv_bfloat16* __restrict__ Bw,
             const float* __restrict__ bias, const float* __restrict__ resid,
             void* __restrict__ CoutV, int K, int Ncols) {
    extern __shared__ __align__(1024) unsigned char smem[];
    uint32_t sb = smem_u32(smem);
    int* rowIdx = (int*)(smem + 2*STG);

    int tid = threadIdx.x;
    int rowBase = blockIdx.y * 128;
    int colBase = blockIdx.x * 96;

    if (tid < 128) {
        int r = rowBase + tid;
        rowIdx[tid] = (MODE == 0) ? win_to_img_row(r) : r;
    }
    __syncthreads();

    int lc = tid & 7;
    int lr0 = tid >> 3;
    const char* aPtr[4]; uint32_t aDst[4];
    #pragma unroll
    for (int i = 0; i < 4; i++) {
        int r = lr0 + 32*i;
        aPtr[i] = (const char*)(A + (size_t)rowIdx[r]*K + 8*lc);
        aDst[i] = (uint32_t)(r*128 + ((lc ^ (r & 7)) << 4));
    }
    const char* bPtr[3]; uint32_t bDst[3];
    #pragma unroll
    for (int i = 0; i < 3; i++) {
        int r = lr0 + 32*i;
        bPtr[i] = (const char*)(Bw + (size_t)(colBase + r)*K + 8*lc);
        bDst[i] = (uint32_t)(r*128 + ((lc ^ (r & 7)) << 4));
    }

    const int T = K >> 6;
    {
        #pragma unroll
        for (int i = 0; i < 4; i++) cp16(sb + aDst[i], aPtr[i]);
        #pragma unroll
        for (int i = 0; i < 3; i++) cp16(sb + BOFF + bDst[i], bPtr[i]);
        CP_COMMIT();
        #pragma unroll
        for (int i = 0; i < 4; i++) cp16(sb + STG + aDst[i], aPtr[i] + 128);
        #pragma unroll
        for (int i = 0; i < 3; i++) cp16(sb + STG + BOFF + bDst[i], bPtr[i] + 128);
        CP_COMMIT();
    }

    int w = tid >> 5, lane = tid & 31;
    int wm = w >> 1, wn = w & 1;
    int mW = wm * 32, nW = wn * 48;
    int q  = lane >> 3, lrl = lane & 7;
    int qh = q >> 1, ql = q & 1;

    int aRow[2];
    #pragma unroll
    for (int mt = 0; mt < 2; mt++) aRow[mt] = mW + 16*mt + ql*8 + lrl;
    int bRow[3];
    #pragma unroll
    for (int p = 0; p < 3; p++) bRow[p] = nW + 8*(2*p + qh) + lrl;

    float acc[2][6][4];
    #pragma unroll
    for (int mt = 0; mt < 2; mt++)
        #pragma unroll
        for (int nt = 0; nt < 6; nt++)
            #pragma unroll
            for (int i = 0; i < 4; i++) acc[mt][nt][i] = 0.f;

    for (int t = 0; t < T; t++) {
        if (t + 1 < T) { CP_WAIT(1); } else { CP_WAIT(0); }
        __syncthreads();

        uint32_t aB = sb + (uint32_t)(t & 1) * STG;
        uint32_t bB = aB + BOFF;

        #pragma unroll
        for (int kk = 0; kk < 4; kk++) {
            int ck = kk * 2;
            unsigned aF[2][4], bF[6][2];
            #pragma unroll
            for (int mt = 0; mt < 2; mt++) {
                int ch = ck + qh;
                uint32_t ad = aB + (uint32_t)(aRow[mt]*128 + (((ch ^ (aRow[mt] & 7)) << 4)));
                LDSM4(aF[mt][0], aF[mt][1], aF[mt][2], aF[mt][3], ad);
            }
            #pragma unroll
            for (int p = 0; p < 3; p++) {
                int ch = ck + ql;
                uint32_t bd = bB + (uint32_t)(bRow[p]*128 + (((ch ^ (bRow[p] & 7)) << 4)));
                LDSM4(bF[2*p][0], bF[2*p][1], bF[2*p+1][0], bF[2*p+1][1], bd);
            }
            #pragma unroll
            for (int mt = 0; mt < 2; mt++)
                #pragma unroll
                for (int nt = 0; nt < 6; nt++)
                    mma_bf16(acc[mt][nt], aF[mt], bF[nt]);
        }

        if (t + 2 < T) {
            __syncthreads();
            int k0 = (t + 2) << 7;
            uint32_t dB = sb + (uint32_t)(t & 1) * STG;
            #pragma unroll
            for (int i = 0; i < 4; i++) cp16(dB + aDst[i], aPtr[i] + k0);
            #pragma unroll
            for (int i = 0; i < 3; i++) cp16(dB + BOFF + bDst[i], bPtr[i] + k0);
            CP_COMMIT();
        }
    }

    int g  = lane >> 2, tg = lane & 3;
    float*         CoutF = (float*)CoutV;
    __nv_bfloat16* CoutB = (__nv_bfloat16*)CoutV;
    #pragma unroll
    for (int mt = 0; mt < 2; mt++) {
        #pragma unroll
        for (int half = 0; half < 2; half++) {
            int row = rowBase + mW + 16*mt + g + half*8;
            int dst = (MODE == 1) ? win_to_img_row(row) : row;
            #pragma unroll
            for (int nt = 0; nt < 6; nt++) {
                int col = colBase + nW + 8*nt + 2*tg;
                float2 bb = *(const float2*)&bias[col];
                float v0 = acc[mt][nt][half*2 + 0] + bb.x;
                float v1 = acc[mt][nt][half*2 + 1] + bb.y;
                if (MODE == 1 || MODE == 3) {
                    float2 rr = *(const float2*)&resid[(size_t)dst*Ncols + col];
                    float2 o; o.x = rr.x + v0; o.y = rr.y + v1;
                    *(float2*)&CoutF[(size_t)dst*Ncols + col] = o;
                } else if (MODE == 2) {
                    float o0 = 0.5f * v0 * (1.0f + erff(v0 * 0.70710678118654752f));
                    float o1 = 0.5f * v1 * (1.0f + erff(v1 * 0.70710678118654752f));
                    *(__nv_bfloat162*)&CoutB[(size_t)dst*Ncols + col] = __floats2bfloat162_rn(o0, o1);
                } else {
                    *(__nv_bfloat162*)&CoutB[(size_t)dst*Ncols + col] = __floats2bfloat162_rn(v0, v1);
                }
            }
        }
    }
}

// ---------------- tensor-core attention: one block per window, 256 threads ----------------
__device__ __forceinline__ int region_of(int p) {
    return (p < 56) ? 0 : ((p < 60) ? 1 : 2);
}

// smem: qkv tile 64x576 bf16 swizzled (73728 B) + rpb (5400 B) + region LUT (256 B)
#define ASM_QKV  0
#define ASM_RPB  73728
#define ASM_REG  (73728 + 5400)
#define ASM_TOT  (73728 + 5400 + 256)

__global__ __launch_bounds__(256)
void attn_mma(const __nv_bfloat16* __restrict__ qkv, const float* __restrict__ rpb,
              __nv_bfloat16* __restrict__ out) {
    extern __shared__ __align__(1024) unsigned char sm[];
    uint32_t sb = smem_u32(sm);
    float* rpbs = (float*)(sm + ASM_RPB);
    int*   regl = (int*)(sm + ASM_REG);

    int tid = threadIdx.x;
    int win = blockIdx.x;
    int rowbase = win * 64;

    // load qkv tile (64 rows x 72 16B-chunks), XOR-swizzled within 128B groups
    #pragma unroll
    for (int i = 0; i < 18; i++) {
        int id = tid + i*256;
        int r = id / 72, c = id % 72;
        uint32_t dst = sb + (uint32_t)(r*1152 + (((c & ~7) | ((c & 7) ^ (r & 7))) << 4));
        cp16(dst, qkv + (size_t)(rowbase + r)*576 + c*8);
    }
    CP_COMMIT();
    for (int i = tid; i < 225*NHEAD; i += 256) rpbs[i] = rpb[i];
    if (tid < 64) {
        int wr = (win & 63) >> 3, wc = win & 7;
        regl[tid] = region_of(wr*8 + (tid >> 3))*3 + region_of(wc*8 + (tid & 7));
    }
    CP_WAIT(0);
    __syncthreads();

    int w = tid >> 5, lane = tid & 31;
    int q  = lane >> 3, lrl = lane & 7;
    int qh = q >> 1,   ql  = q & 1;
    int g  = lane >> 2, tg = lane & 3;

    for (int task = w; task < 24; task += 8) {
        int h = task >> 2, mt = task & 3;

        // ---- S = q k^T  (S[16,64], fp32 frags) ----
        float sF[8][4];
        #pragma unroll
        for (int nt = 0; nt < 8; nt++)
            #pragma unroll
            for (int i = 0; i < 4; i++) sF[nt][i] = 0.f;

        #pragma unroll
        for (int kk = 0; kk < 2; kk++) {
            unsigned aF[4];
            {
                int r = mt*16 + ql*8 + lrl;
                int c = 4*h + 2*kk + qh;
                LDSM4(aF[0], aF[1], aF[2], aF[3],
                      sb + (uint32_t)(r*1152 + (((c & ~7) | ((c & 7) ^ (r & 7))) << 4)));
            }
            #pragma unroll
            for (int p = 0; p < 4; p++) {
                unsigned b0, b1, b2, b3;
                int r = 16*p + qh*8 + lrl;
                int c = 24 + 4*h + 2*kk + ql;
                LDSM4(b0, b1, b2, b3,
                      sb + (uint32_t)(r*1152 + (((c & ~7) | ((c & 7) ^ (r & 7))) << 4)));
                unsigned bb0[2] = {b0, b1}, bb1[2] = {b2, b3};
                mma_bf16(sF[2*p],   aF, bb0);
                mma_bf16(sF[2*p+1], aF, bb1);
            }
        }

        // ---- scale + bias + mask + softmax (rows n0 = c0/c1, n1 = c2/c3) ----
        int n0 = mt*16 + g, n1 = n0 + 8;
        int r0g = regl[n0], r1g = regl[n1];
        int in0 = n0 >> 3, jn0 = n0 & 7;
        int in1 = n1 >> 3, jn1 = n1 & 7;
        const float scale = 0.17677669529663687f;
        float mx0 = -1e30f, mx1 = -1e30f;
        #pragma unroll
        for (int nt = 0; nt < 8; nt++) {
            #pragma unroll
            for (int e = 0; e < 2; e++) {
                int col = nt*8 + 2*tg + e;
                int im = col >> 3, jm = col & 7;
                int rm = regl[col];
                float bv0 = rpbs[((in0 - im + 7)*15 + (jn0 - jm + 7))*NHEAD + h];
                float bv1 = rpbs[((in1 - im + 7)*15 + (jn1 - jm + 7))*NHEAD + h];
                float v0 = sF[nt][e]   * scale + bv0 + ((r0g == rm) ? 0.f : -100.f);
                float v1 = sF[nt][2+e] * scale + bv1 + ((r1g == rm) ? 0.f : -100.f);
                sF[nt][e] = v0; sF[nt][2+e] = v1;
                mx0 = fmaxf(mx0, v0); mx1 = fmaxf(mx1, v1);
            }
        }
        mx0 = fmaxf(mx0, __shfl_xor_sync(0xffffffffu, mx0, 1));
        mx0 = fmaxf(mx0, __shfl_xor_sync(0xffffffffu, mx0, 2));
        mx1 = fmaxf(mx1, __shfl_xor_sync(0xffffffffu, mx1, 1));
        mx1 = fmaxf(mx1, __shfl_xor_sync(0xffffffffu, mx1, 2));
        float s0 = 0.f, s1 = 0.f;
        #pragma unroll
        for (int nt = 0; nt < 8; nt++) {
            #pragma unroll
            for (int e = 0; e < 2; e++) {
                float e0 = __expf(sF[nt][e]   - mx0);
                float e1 = __expf(sF[nt][2+e] - mx1);
                sF[nt][e] = e0;   s0 += e0;
                sF[nt][2+e] = e1; s1 += e1;
            }
        }
        s0 += __shfl_xor_sync(0xffffffffu, s0, 1);
        s0 += __shfl_xor_sync(0xffffffffu, s0, 2);
        s1 += __shfl_xor_sync(0xffffffffu, s1, 1);
        s1 += __shfl_xor_sync(0xffffffffu, s1, 2);

        // ---- O = P V  (P frags reused in-register; V^T via ldmatrix.trans) ----
        float oF[4][4];
        #pragma unroll
        for (int nt = 0; nt < 4; nt++)
            #pragma unroll
            for (int i = 0; i < 4; i++) oF[nt][i] = 0.f;

        #pragma unroll
        for (int kk = 0; kk < 4; kk++) {
            unsigned pA[4];
            pA[0] = pack_bf16(sF[2*kk][0],   sF[2*kk][1]);
            pA[1] = pack_bf16(sF[2*kk][2],   sF[2*kk][3]);
            pA[2] = pack_bf16(sF[2*kk+1][0], sF[2*kk+1][1]);
            pA[3] = pack_bf16(sF[2*kk+1][2], sF[2*kk+1][3]);
            #pragma unroll
            for (int dh = 0; dh < 2; dh++) {
                unsigned b0, b1, b2, b3;
                int r = 16*kk + ql*8 + lrl;
                int c = 48 + 4*h + 2*dh + qh;
                LDSM4T(b0, b1, b2, b3,
                       sb + (uint32_t)(r*1152 + (((c & ~7) | ((c & 7) ^ (r & 7))) << 4)));
                unsigned bb0[2] = {b0, b1}, bb1[2] = {b2, b3};
                mma_bf16(oF[2*dh],   pA, bb0);
                mma_bf16(oF[2*dh+1], pA, bb1);
            }
        }

        float rs0 = 1.0f / s0, rs1 = 1.0f / s1;
        #pragma unroll
        for (int nt = 0; nt < 4; nt++) {
            int col = h*32 + nt*8 + 2*tg;
            size_t t0 = (size_t)(rowbase + n0)*CH + col;
            size_t t1 = (size_t)(rowbase + n1)*CH + col;
            *(__nv_bfloat162*)&out[t0] = __floats2bfloat162_rn(oF[nt][0]*rs0, oF[nt][1]*rs0);
            *(__nv_bfloat162*)&out[t1] = __floats2bfloat162_rn(oF[nt][2]*rs1, oF[nt][3]*rs1);
        }
    }
}

// ---------------- launch ----------------
extern "C" void kernel_launch(void* const* d_in, const int* in_sizes, int n_in,
                              void* d_out, int out_size) {
    const float* x       = (const float*)d_in[0];
    const float* norm1_g = (const float*)d_in[3];
    const float* norm1_b = (const float*)d_in[4];
    const float* qkv_w   = (const float*)d_in[5];
    const float* qkv_b   = (const float*)d_in[6];
    const float* rpb     = (const float*)d_in[7];
    const float* proj_w  = (const float*)d_in[8];
    const float* proj_b  = (const float*)d_in[9];
    const float* norm2_g = (const float*)d_in[10];
    const float* norm2_b = (const float*)d_in[11];
    const float* fc1_w   = (const float*)d_in[12];
    const float* fc1_b   = (const float*)d_in[13];
    const float* fc2_w   = (const float*)d_in[14];
    const float* fc2_b   = (const float*)d_in[15];
    float* out = (float*)d_out;

    __nv_bfloat16 *xn, *qkv, *attn, *xn2, *h1, *wq, *wp, *w1, *w2;
    float *x2;
    cudaGetSymbolAddress((void**)&xn,   g_xn);
    cudaGetSymbolAddress((void**)&qkv,  g_qkv);
    cudaGetSymbolAddress((void**)&attn, g_attn);
    cudaGetSymbolAddress((void**)&x2,   g_x2);
    cudaGetSymbolAddress((void**)&xn2,  g_xn2);
    cudaGetSymbolAddress((void**)&h1,   g_h1);
    cudaGetSymbolAddress((void**)&wq,   g_wq);
    cudaGetSymbolAddress((void**)&wp,   g_wp);
    cudaGetSymbolAddress((void**)&w1,   g_w1);
    cudaGetSymbolAddress((void**)&w2,   g_w2);

    cudaFuncSetAttribute(gemm_lm<0>, cudaFuncAttributeMaxDynamicSharedMemorySize, GSM);
    cudaFuncSetAttribute(gemm_lm<1>, cudaFuncAttributeMaxDynamicSharedMemorySize, GSM);
    cudaFuncSetAttribute(gemm_lm<2>, cudaFuncAttributeMaxDynamicSharedMemorySize, GSM);
    cudaFuncSetAttribute(gemm_lm<3>, cudaFuncAttributeMaxDynamicSharedMemorySize, GSM);
    cudaFuncSetAttribute(attn_mma,   cudaFuncAttributeMaxDynamicSharedMemorySize, ASM_TOT);

    // 0) all weights -> bf16
    cvt_all<<<(NWQ+NWP+NW1+NW2)/1024, 256>>>(qkv_w, proj_w, fc1_w, fc2_w, wq, wp, w1, w2);
    // 1) LN1
    ln_kernel<<<MROWS/8, 256>>>(x, norm1_g, norm1_b, xn);
    // 2) QKV (gathered A: shift + window partition fused)
    gemm_lm<0><<<dim3(6, MROWS/128), 256, GSM>>>(xn, wq, qkv_b, nullptr, qkv, CH, 3*CH);
    // 3) windowed attention (tensor cores)
    attn_mma<<<BATCH*NWIN, 256, ASM_TOT>>>(qkv, rpb, attn);
    // 4) proj + window reverse + roll + residual
    gemm_lm<1><<<dim3(2, MROWS/128), 256, GSM>>>(attn, wp, proj_b, x, x2, CH, CH);
    // 5) LN2
    ln_kernel<<<MROWS/8, 256>>>(x2, norm2_g, norm2_b, xn2);
    // 6) fc1 + GELU
    gemm_lm<2><<<dim3(8, MROWS/128), 256, GSM>>>(xn2, w1, fc1_b, nullptr, h1, CH, CHID);
    // 7) fc2 + residual -> out
    gemm_lm<3><<<dim3(2, MROWS/128), 256, GSM>>>(h1, w2, fc2_b, x2, out, CHID, CH);
}

// round 13
// speedup vs baseline: 2.6161x; 1.0070x over previous
#include <cuda_runtime.h>
#include <cuda_bf16.h>
#include <math.h>
#include <stdint.h>

// ---------------- problem constants ----------------
#define BATCH 32
#define HH 64
#define WW 64
#define CH 192
#define LL (HH*WW)            // 4096
#define NHEAD 6
#define HD 32
#define WSZ 8
#define SHIFT 4
#define NTOK 64
#define NWIN 64
#define MROWS (BATCH*LL)      // 131072
#define CHID (4*CH)           // 768

// ---------------- scratch (device globals; no allocs allowed) ----------------
__device__ __nv_bfloat16 g_xn  [MROWS*CH];
__device__ __nv_bfloat16 g_qkv [MROWS*3*CH];
__device__ __nv_bfloat16 g_attn[MROWS*CH];
__device__ float         g_x2  [MROWS*CH];
__device__ __nv_bfloat16 g_xn2 [MROWS*CH];
__device__ __nv_bfloat16 g_h1  [MROWS*CHID];
// bf16 weights (converted once per launch)
__device__ __nv_bfloat16 g_wq[3*CH*CH];
__device__ __nv_bfloat16 g_wp[CH*CH];
__device__ __nv_bfloat16 g_w1[CHID*CH];
__device__ __nv_bfloat16 g_w2[CH*CHID];

// roll(-4,-4)+window-partition map (self-inverse)
__device__ __forceinline__ int win_to_img_row(int r) {
    int b   = r >> 12;
    int rem = r & 4095;
    int win = rem >> 6;
    int n   = rem & 63;
    int hs  = ((win >> 3) << 3) + (n >> 3);
    int ws  = ((win & 7)  << 3) + (n & 7);
    int hh  = (hs + SHIFT) & 63;
    int ww  = (ws + SHIFT) & 63;
    return (b << 12) + (hh << 6) + ww;
}

// ---------------- asm helpers ----------------
__device__ __forceinline__ uint32_t smem_u32(const void* p) {
    uint32_t a;
    asm("{ .reg .u64 t; cvta.to.shared.u64 t, %1; cvt.u32.u64 %0, t; }" : "=r"(a) : "l"(p));
    return a;
}
__device__ __forceinline__ void cp16(uint32_t dst, const void* src) {
    asm volatile("cp.async.cg.shared.global [%0], [%1], 16;" :: "r"(dst), "l"(src));
}
#define CP_COMMIT() asm volatile("cp.async.commit_group;" ::: "memory")
#define CP_WAIT(n)  asm volatile("cp.async.wait_group %0;" :: "n"(n) : "memory")
#define LDSM4(r0, r1, r2, r3, a) \
    asm volatile("ldmatrix.sync.aligned.m8n8.x4.shared.b16 {%0,%1,%2,%3}, [%4];" \
                 : "=r"(r0), "=r"(r1), "=r"(r2), "=r"(r3) : "r"(a))
#define LDSM4T(r0, r1, r2, r3, a) \
    asm volatile("ldmatrix.sync.aligned.m8n8.x4.trans.shared.b16 {%0,%1,%2,%3}, [%4];" \
                 : "=r"(r0), "=r"(r1), "=r"(r2), "=r"(r3) : "r"(a))

__device__ __forceinline__ void mma_bf16(float* d, const unsigned* a, const unsigned* b) {
    asm volatile(
        "mma.sync.aligned.m16n8k16.row.col.f32.bf16.bf16.f32 "
        "{%0,%1,%2,%3}, {%4,%5,%6,%7}, {%8,%9}, {%0,%1,%2,%3};"
        : "+f"(d[0]), "+f"(d[1]), "+f"(d[2]), "+f"(d[3])
        : "r"(a[0]), "r"(a[1]), "r"(a[2]), "r"(a[3]), "r"(b[0]), "r"(b[1]));
}
__device__ __forceinline__ unsigned pack_bf16(float lo, float hi) {
    __nv_bfloat162 h = __floats2bfloat162_rn(lo, hi);
    return *(unsigned*)&h;
}

// ---------------- fused fp32 -> bf16 weight conversion ----------------
#define NWQ (3*CH*CH)
#define NWP (CH*CH)
#define NW1 (CHID*CH)
#define NW2 (CH*CHID)
__global__ void cvt_all(const float* __restrict__ wq, const float* __restrict__ wp,
                        const float* __restrict__ w1, const float* __restrict__ w2,
                        __nv_bfloat16* __restrict__ dq, __nv_bfloat16* __restrict__ dp,
                        __nv_bfloat16* __restrict__ d1, __nv_bfloat16* __restrict__ d2) {
    int i = (blockIdx.x * 256 + threadIdx.x) * 4;
    const float* s; __nv_bfloat16* d; int off;
    if (i < NWQ)                       { s = wq; d = dq; off = i; }
    else if (i < NWQ+NWP)              { s = wp; d = dp; off = i - NWQ; }
    else if (i < NWQ+NWP+NW1)          { s = w1; d = d1; off = i - NWQ - NWP; }
    else if (i < NWQ+NWP+NW1+NW2)      { s = w2; d = d2; off = i - NWQ - NWP - NW1; }
    else return;
    float4 v = *(const float4*)&s[off];
    *(__nv_bfloat162*)&d[off]   = __floats2bfloat162_rn(v.x, v.y);
    *(__nv_bfloat162*)&d[off+2] = __floats2bfloat162_rn(v.z, v.w);
}

// ---------------- LayerNorm: one warp per row ----------------
__global__ __launch_bounds__(256)
void ln_kernel(const float* __restrict__ x, const float* __restrict__ g,
               const float* __restrict__ b, __nv_bfloat16* __restrict__ out) {
    int w = threadIdx.x >> 5, lane = threadIdx.x & 31;
    int row = blockIdx.x * 8 + w;
    const float* xr = x + (size_t)row * CH;
    float v[6];
    float s = 0.f, s2 = 0.f;
    #pragma unroll
    for (int i = 0; i < 6; i++) {
        v[i] = xr[lane + 32*i];
        s  += v[i];
        s2 += v[i]*v[i];
    }
    #pragma unroll
    for (int o = 16; o > 0; o >>= 1) {
        s  += __shfl_xor_sync(0xffffffffu, s,  o);
        s2 += __shfl_xor_sync(0xffffffffu, s2, o);
    }
    float mean = s * (1.0f/CH);
    float var  = s2 * (1.0f/CH) - mean*mean;
    float inv  = rsqrtf(var + 1e-5f);
    __nv_bfloat16* orow = out + (size_t)row * CH;
    #pragma unroll
    for (int i = 0; i < 6; i++) {
        int c = lane + 32*i;
        orow[c] = __float2bfloat16((v[i] - mean) * inv * g[c] + b[c]);
    }
}

// ---------------- bf16 mma GEMM: 3-stage cp.async, single sync/iter ----------------
// 256 threads = 8 warps (4m x 2n), BM=128, BN=96, BK=64, warp tile 32x48.
// 3 smem stages of (A 16KB + B 12KB). Iter t: wait stage t, sync, issue stage
// t+2 into buffer (t+2)%3 == (t-1)%3 (its readers are provably past the sync),
// compute buffer t%3. One __syncthreads per iteration.
#define STG   28672
#define BOFF  16384
#define GSM   (3*STG + 512)

template<int MODE>
__global__ __launch_bounds__(256, 2)
void gemm_lm(const __nv_bfloat16* __restrict__ A, const __nv_bfloat16* __restrict__ Bw,
             const float* __restrict__ bias, const float* __restrict__ resid,
             void* __restrict__ CoutV, int K, int Ncols) {
    extern __shared__ __align__(1024) unsigned char smem[];
    uint32_t sb = smem_u32(smem);
    int* rowIdx = (int*)(smem + 3*STG);

    int tid = threadIdx.x;
    int rowBase = blockIdx.y * 128;
    int colBase = blockIdx.x * 96;

    if (tid < 128) {
        int r = rowBase + tid;
        rowIdx[tid] = (MODE == 0) ? win_to_img_row(r) : r;
    }
    __syncthreads();

    int lc = tid & 7;
    int lr0 = tid >> 3;
    const char* aPtr[4]; uint32_t aDst[4];
    #pragma unroll
    for (int i = 0; i < 4; i++) {
        int r = lr0 + 32*i;
        aPtr[i] = (const char*)(A + (size_t)rowIdx[r]*K + 8*lc);
        aDst[i] = (uint32_t)(r*128 + ((lc ^ (r & 7)) << 4));
    }
    const char* bPtr[3]; uint32_t bDst[3];
    #pragma unroll
    for (int i = 0; i < 3; i++) {
        int r = lr0 + 32*i;
        bPtr[i] = (const char*)(Bw + (size_t)(colBase + r)*K + 8*lc);
        bDst[i] = (uint32_t)(r*128 + ((lc ^ (r & 7)) << 4));
    }

    const int T = K >> 6;

    // prologue: stages 0,1
    {
        #pragma unroll
        for (int i = 0; i < 4; i++) cp16(sb + aDst[i], aPtr[i]);
        #pragma unroll
        for (int i = 0; i < 3; i++) cp16(sb + BOFF + bDst[i], bPtr[i]);
        CP_COMMIT();
        #pragma unroll
        for (int i = 0; i < 4; i++) cp16(sb + STG + aDst[i], aPtr[i] + 128);
        #pragma unroll
        for (int i = 0; i < 3; i++) cp16(sb + STG + BOFF + bDst[i], bPtr[i] + 128);
        CP_COMMIT();
    }

    int w = tid >> 5, lane = tid & 31;
    int wm = w >> 1, wn = w & 1;
    int mW = wm * 32, nW = wn * 48;
    int q  = lane >> 3, lrl = lane & 7;
    int qh = q >> 1, ql = q & 1;

    int aRow[2];
    #pragma unroll
    for (int mt = 0; mt < 2; mt++) aRow[mt] = mW + 16*mt + ql*8 + lrl;
    int bRow[3];
    #pragma unroll
    for (int p = 0; p < 3; p++) bRow[p] = nW + 8*(2*p + qh) + lrl;

    float acc[2][6][4];
    #pragma unroll
    for (int mt = 0; mt < 2; mt++)
        #pragma unroll
        for (int nt = 0; nt < 6; nt++)
            #pragma unroll
            for (int i = 0; i < 4; i++) acc[mt][nt][i] = 0.f;

    int cBuf = 0, wBuf = 2;
    for (int t = 0; t < T; t++) {
        if (t + 1 < T) { CP_WAIT(1); } else { CP_WAIT(0); }
        __syncthreads();

        if (t + 2 < T) {
            int k0 = (t + 2) << 7;            // bytes: 64 bf16 = 128B
            uint32_t dB = sb + (uint32_t)wBuf * STG;
            #pragma unroll
            for (int i = 0; i < 4; i++) cp16(dB + aDst[i], aPtr[i] + k0);
            #pragma unroll
            for (int i = 0; i < 3; i++) cp16(dB + BOFF + bDst[i], bPtr[i] + k0);
            CP_COMMIT();
        }

        uint32_t aB = sb + (uint32_t)cBuf * STG;
        uint32_t bB = aB + BOFF;

        #pragma unroll
        for (int kk = 0; kk < 4; kk++) {
            int ck = kk * 2;
            unsigned aF[2][4], bF[6][2];
            #pragma unroll
            for (int mt = 0; mt < 2; mt++) {
                int ch = ck + qh;
                uint32_t ad = aB + (uint32_t)(aRow[mt]*128 + (((ch ^ (aRow[mt] & 7)) << 4)));
                LDSM4(aF[mt][0], aF[mt][1], aF[mt][2], aF[mt][3], ad);
            }
            #pragma unroll
            for (int p = 0; p < 3; p++) {
                int ch = ck + ql;
                uint32_t bd = bB + (uint32_t)(bRow[p]*128 + (((ch ^ (bRow[p] & 7)) << 4)));
                LDSM4(bF[2*p][0], bF[2*p][1], bF[2*p+1][0], bF[2*p+1][1], bd);
            }
            #pragma unroll
            for (int mt = 0; mt < 2; mt++)
                #pragma unroll
                for (int nt = 0; nt < 6; nt++)
                    mma_bf16(acc[mt][nt], aF[mt], bF[nt]);
        }

        cBuf = (cBuf == 2) ? 0 : cBuf + 1;
        wBuf = (wBuf == 2) ? 0 : wBuf + 1;
    }

    int g  = lane >> 2, tg = lane & 3;
    float*         CoutF = (float*)CoutV;
    __nv_bfloat16* CoutB = (__nv_bfloat16*)CoutV;
    #pragma unroll
    for (int mt = 0; mt < 2; mt++) {
        #pragma unroll
        for (int half = 0; half < 2; half++) {
            int row = rowBase + mW + 16*mt + g + half*8;
            int dst = (MODE == 1) ? win_to_img_row(row) : row;
            #pragma unroll
            for (int nt = 0; nt < 6; nt++) {
                int col = colBase + nW + 8*nt + 2*tg;
                float2 bb = *(const float2*)&bias[col];
                float v0 = acc[mt][nt][half*2 + 0] + bb.x;
                float v1 = acc[mt][nt][half*2 + 1] + bb.y;
                if (MODE == 1 || MODE == 3) {
                    float2 rr = *(const float2*)&resid[(size_t)dst*Ncols + col];
                    float2 o; o.x = rr.x + v0; o.y = rr.y + v1;
                    *(float2*)&CoutF[(size_t)dst*Ncols + col] = o;
                } else if (MODE == 2) {
                    float o0 = 0.5f * v0 * (1.0f + erff(v0 * 0.70710678118654752f));
                    float o1 = 0.5f * v1 * (1.0f + erff(v1 * 0.70710678118654752f));
                    *(__nv_bfloat162*)&CoutB[(size_t)dst*Ncols + col] = __floats2bfloat162_rn(o0, o1);
                } else {
                    *(__nv_bfloat162*)&CoutB[(size_t)dst*Ncols + col] = __floats2bfloat162_rn(v0, v1);
                }
            }
        }
    }
}

// ---------------- tensor-core attention: one block per window, 256 threads ----------------
__device__ __forceinline__ int region_of(int p) {
    return (p < 56) ? 0 : ((p < 60) ? 1 : 2);
}

// smem: qkv tile 64x576 bf16 swizzled (73728 B) + rpb [h][225] (5400 B) + region LUT
#define ASM_RPB  73728
#define ASM_REG  (73728 + 5400)
#define ASM_TOT  (73728 + 5400 + 256)

__global__ __launch_bounds__(256)
void attn_mma(const __nv_bfloat16* __restrict__ qkv, const float* __restrict__ rpb,
              __nv_bfloat16* __restrict__ out) {
    extern __shared__ __align__(1024) unsigned char sm[];
    uint32_t sb = smem_u32(sm);
    float* rpbs = (float*)(sm + ASM_RPB);
    int*   regl = (int*)(sm + ASM_REG);

    int tid = threadIdx.x;
    int win = blockIdx.x;
    int rowbase = win * 64;

    #pragma unroll
    for (int i = 0; i < 18; i++) {
        int id = tid + i*256;
        int r = id / 72, c = id % 72;
        uint32_t dst = sb + (uint32_t)(r*1152 + (((c & ~7) | ((c & 7) ^ (r & 7))) << 4));
        cp16(dst, qkv + (size_t)(rowbase + r)*576 + c*8);
    }
    CP_COMMIT();
    // rpb transposed to [h][225] for cheap indexing
    for (int i = tid; i < 225*NHEAD; i += 256) {
        int idx = i / NHEAD, h = i % NHEAD;
        rpbs[h*225 + idx] = rpb[i];
    }
    if (tid < 64) {
        int wr = (win & 63) >> 3, wc = win & 7;
        regl[tid] = region_of(wr*8 + (tid >> 3))*3 + region_of(wc*8 + (tid & 7));
    }
    CP_WAIT(0);
    __syncthreads();

    int w = tid >> 5, lane = tid & 31;
    int q  = lane >> 3, lrl = lane & 7;
    int qh = q >> 1,   ql  = q & 1;
    int g  = lane >> 2, tg = lane & 3;

    for (int task = w; task < 24; task += 8) {
        int h = task >> 2, mt = task & 3;

        // ---- S = q k^T ----
        float sF[8][4];
        #pragma unroll
        for (int nt = 0; nt < 8; nt++)
            #pragma unroll
            for (int i = 0; i < 4; i++) sF[nt][i] = 0.f;

        #pragma unroll
        for (int kk = 0; kk < 2; kk++) {
            unsigned aF[4];
            {
                int r = mt*16 + ql*8 + lrl;
                int c = 4*h + 2*kk + qh;
                LDSM4(aF[0], aF[1], aF[2], aF[3],
                      sb + (uint32_t)(r*1152 + (((c & ~7) | ((c & 7) ^ (r & 7))) << 4)));
            }
            #pragma unroll
            for (int p = 0; p < 4; p++) {
                unsigned b0, b1, b2, b3;
                int r = 16*p + qh*8 + lrl;
                int c = 24 + 4*h + 2*kk + ql;
                LDSM4(b0, b1, b2, b3,
                      sb + (uint32_t)(r*1152 + (((c & ~7) | ((c & 7) ^ (r & 7))) << 4)));
                unsigned bb0[2] = {b0, b1}, bb1[2] = {b2, b3};
                mma_bf16(sF[2*p],   aF, bb0);
                mma_bf16(sF[2*p+1], aF, bb1);
            }
        }

        // ---- scale + bias + mask + softmax ----
        // col = nt*8 + 2*tg + e  =>  im = nt, jm = 2*tg + e  (col < 64)
        int n0 = mt*16 + g, n1 = n0 + 8;
        int r0g = regl[n0], r1g = regl[n1];
        int in0 = n0 >> 3, jn0 = n0 & 7;
        int in1 = n1 >> 3, jn1 = n1 & 7;
        const float* rh = rpbs + h*225;
        int jb0 = jn0 + 7 - 2*tg;           // bias col-part for e=0; e=1 -> -1
        int jb1 = jn1 + 7 - 2*tg;
        const float scale = 0.17677669529663687f;
        float mx0 = -1e30f, mx1 = -1e30f;
        #pragma unroll
        for (int nt = 0; nt < 8; nt++) {
            const float* r0p = rh + (in0 - nt + 7)*15 + jb0;
            const float* r1p = rh + (in1 - nt + 7)*15 + jb1;
            #pragma unroll
            for (int e = 0; e < 2; e++) {
                int col = nt*8 + 2*tg + e;
                int rm = regl[col];
                float v0 = sF[nt][e]   * scale + r0p[-e] + ((r0g == rm) ? 0.f : -100.f);
                float v1 = sF[nt][2+e] * scale + r1p[-e] + ((r1g == rm) ? 0.f : -100.f);
                sF[nt][e] = v0; sF[nt][2+e] = v1;
                mx0 = fmaxf(mx0, v0); mx1 = fmaxf(mx1, v1);
            }
        }
        mx0 = fmaxf(mx0, __shfl_xor_sync(0xffffffffu, mx0, 1));
        mx0 = fmaxf(mx0, __shfl_xor_sync(0xffffffffu, mx0, 2));
        mx1 = fmaxf(mx1, __shfl_xor_sync(0xffffffffu, mx1, 1));
        mx1 = fmaxf(mx1, __shfl_xor_sync(0xffffffffu, mx1, 2));
        float s0 = 0.f, s1 = 0.f;
        #pragma unroll
        for (int nt = 0; nt < 8; nt++) {
            #pragma unroll
            for (int e = 0; e < 2; e++) {
                float e0 = __expf(sF[nt][e]   - mx0);
                float e1 = __expf(sF[nt][2+e] - mx1);
                sF[nt][e] = e0;   s0 += e0;
                sF[nt][2+e] = e1; s1 += e1;
            }
        }
        s0 += __shfl_xor_sync(0xffffffffu, s0, 1);
        s0 += __shfl_xor_sync(0xffffffffu, s0, 2);
        s1 += __shfl_xor_sync(0xffffffffu, s1, 1);
        s1 += __shfl_xor_sync(0xffffffffu, s1, 2);

        // ---- O = P V ----
        float oF[4][4];
        #pragma unroll
        for (int nt = 0; nt < 4; nt++)
            #pragma unroll
            for (int i = 0; i < 4; i++) oF[nt][i] = 0.f;

        #pragma unroll
        for (int kk = 0; kk < 4; kk++) {
            unsigned pA[4];
            pA[0] = pack_bf16(sF[2*kk][0],   sF[2*kk][1]);
            pA[1] = pack_bf16(sF[2*kk][2],   sF[2*kk][3]);
            pA[2] = pack_bf16(sF[2*kk+1][0], sF[2*kk+1][1]);
            pA[3] = pack_bf16(sF[2*kk+1][2], sF[2*kk+1][3]);
            #pragma unroll
            for (int dh = 0; dh < 2; dh++) {
                unsigned b0, b1, b2, b3;
                int r = 16*kk + ql*8 + lrl;
                int c = 48 + 4*h + 2*dh + qh;
                LDSM4T(b0, b1, b2, b3,
                       sb + (uint32_t)(r*1152 + (((c & ~7) | ((c & 7) ^ (r & 7))) << 4)));
                unsigned bb0[2] = {b0, b1}, bb1[2] = {b2, b3};
                mma_bf16(oF[2*dh],   pA, bb0);
                mma_bf16(oF[2*dh+1], pA, bb1);
            }
        }

        float rs0 = 1.0f / s0, rs1 = 1.0f / s1;
        #pragma unroll
        for (int nt = 0; nt < 4; nt++) {
            int col = h*32 + nt*8 + 2*tg;
            size_t t0 = (size_t)(rowbase + n0)*CH + col;
            size_t t1 = (size_t)(rowbase + n1)*CH + col;
            *(__nv_bfloat162*)&out[t0] = __floats2bfloat162_rn(oF[nt][0]*rs0, oF[nt][1]*rs0);
            *(__nv_bfloat162*)&out[t1] = __floats2bfloat162_rn(oF[nt][2]*rs1, oF[nt][3]*rs1);
        }
    }
}

// ---------------- launch ----------------
extern "C" void kernel_launch(void* const* d_in, const int* in_sizes, int n_in,
                              void* d_out, int out_size) {
    const float* x       = (const float*)d_in[0];
    const float* norm1_g = (const float*)d_in[3];
    const float* norm1_b = (const float*)d_in[4];
    const float* qkv_w   = (const float*)d_in[5];
    const float* qkv_b   = (const float*)d_in[6];
    const float* rpb     = (const float*)d_in[7];
    const float* proj_w  = (const float*)d_in[8];
    const float* proj_b  = (const float*)d_in[9];
    const float* norm2_g = (const float*)d_in[10];
    const float* norm2_b = (const float*)d_in[11];
    const float* fc1_w   = (const float*)d_in[12];
    const float* fc1_b   = (const float*)d_in[13];
    const float* fc2_w   = (const float*)d_in[14];
    const float* fc2_b   = (const float*)d_in[15];
    float* out = (float*)d_out;

    __nv_bfloat16 *xn, *qkv, *attn, *xn2, *h1, *wq, *wp, *w1, *w2;
    float *x2;
    cudaGetSymbolAddress((void**)&xn,   g_xn);
    cudaGetSymbolAddress((void**)&qkv,  g_qkv);
    cudaGetSymbolAddress((void**)&attn, g_attn);
    cudaGetSymbolAddress((void**)&x2,   g_x2);
    cudaGetSymbolAddress((void**)&xn2,  g_xn2);
    cudaGetSymbolAddress((void**)&h1,   g_h1);
    cudaGetSymbolAddress((void**)&wq,   g_wq);
    cudaGetSymbolAddress((void**)&wp,   g_wp);
    cudaGetSymbolAddress((void**)&w1,   g_w1);
    cudaGetSymbolAddress((void**)&w2,   g_w2);

    cudaFuncSetAttribute(gemm_lm<0>, cudaFuncAttributeMaxDynamicSharedMemorySize, GSM);
    cudaFuncSetAttribute(gemm_lm<1>, cudaFuncAttributeMaxDynamicSharedMemorySize, GSM);
    cudaFuncSetAttribute(gemm_lm<2>, cudaFuncAttributeMaxDynamicSharedMemorySize, GSM);
    cudaFuncSetAttribute(gemm_lm<3>, cudaFuncAttributeMaxDynamicSharedMemorySize, GSM);
    cudaFuncSetAttribute(attn_mma,   cudaFuncAttributeMaxDynamicSharedMemorySize, ASM_TOT);

    // 0) all weights -> bf16
    cvt_all<<<(NWQ+NWP+NW1+NW2)/1024, 256>>>(qkv_w, proj_w, fc1_w, fc2_w, wq, wp, w1, w2);
    // 1) LN1
    ln_kernel<<<MROWS/8, 256>>>(x, norm1_g, norm1_b, xn);
    // 2) QKV (gathered A: shift + window partition fused)
    gemm_lm<0><<<dim3(6, MROWS/128), 256, GSM>>>(xn, wq, qkv_b, nullptr, qkv, CH, 3*CH);
    // 3) windowed attention (tensor cores)
    attn_mma<<<BATCH*NWIN, 256, ASM_TOT>>>(qkv, rpb, attn);
    // 4) proj + window reverse + roll + residual
    gemm_lm<1><<<dim3(2, MROWS/128), 256, GSM>>>(attn, wp, proj_b, x, x2, CH, CH);
    // 5) LN2
    ln_kernel<<<MROWS/8, 256>>>(x2, norm2_g, norm2_b, xn2);
    // 6) fc1 + GELU
    gemm_lm<2><<<dim3(8, MROWS/128), 256, GSM>>>(xn2, w1, fc1_b, nullptr, h1, CH, CHID);
    // 7) fc2 + residual -> out
    gemm_lm<3><<<dim3(2, MROWS/128), 256, GSM>>>(h1, w2, fc2_b, x2, out, CHID, CH);
}